// round 11
// baseline (speedup 1.0000x reference)
#include <cuda_runtime.h>
#include <cuda_bf16.h>
#include <cuda_fp16.h>
#include <cstdint>

#define NMAX 50000
#define EMAX 800000
#define D 128

// ---------------- device scratch (no allocations allowed) ----------------
__device__ int    g_cnt[NMAX];
__device__ int    g_off[NMAX + 1];
__device__ int    g_cur[NMAX];
__device__ int2   g_edge[EMAX];       // {src, attr-bits}
__device__ int    g_bsum[64];
__device__ float  g_h[3][NMAX * D];   // h1, h2, h3 (fp32)
__device__ __half g_hf[3][NMAX * D];  // fp16 shadows: x, h1, h2 (gather sources)
__device__ float  g_tmp[NMAX * D];
// prepacked weight chunks: 40 chunks (6 layer-GEMMs x 4 + final x 16), KB=32.
// chunk = 128 n-rows x 72 bf16 (k 0..31 = hi, 32..63 = lo, 64..71 pad).
__device__ __align__(16) __nv_bfloat16 g_wb[40][128 * 72];

// ---------------- preprocessing: CSR by target + x->fp16 convert ----------------
__global__ void k_hist(const int* __restrict__ tgt, int E,
                       const float* __restrict__ x, int nq) {
    int i = blockIdx.x * blockDim.x + threadIdx.x;
    if (i < E) atomicAdd(&g_cnt[tgt[i]], 1);
    // grid-stride fp32 -> fp16 conversion of x into g_hf[0] (hides under atomics)
    int total = gridDim.x * blockDim.x;
    uint2* xf = (uint2*)g_hf[0];
    for (int j = i; j < nq; j += total) {
        float4 f = ((const float4*)x)[j];
        __half2 a = __float22half2_rn(make_float2(f.x, f.y));
        __half2 b = __float22half2_rn(make_float2(f.z, f.w));
        xf[j] = make_uint2(*(uint32_t*)&a, *(uint32_t*)&b);
    }
}

__device__ __forceinline__ int block_scan_incl(int v) {
    __shared__ int wsum[32];
    const int lane = threadIdx.x & 31;
    const int wid  = threadIdx.x >> 5;
    int s = v;
    #pragma unroll
    for (int d = 1; d < 32; d <<= 1) {
        int t = __shfl_up_sync(0xFFFFFFFFu, s, d);
        if (lane >= d) s += t;
    }
    if (lane == 31) wsum[wid] = s;
    __syncthreads();
    if (wid == 0) {
        int ws = wsum[lane];
        #pragma unroll
        for (int d = 1; d < 32; d <<= 1) {
            int t = __shfl_up_sync(0xFFFFFFFFu, ws, d);
            if (lane >= d) ws += t;
        }
        wsum[lane] = ws;
    }
    __syncthreads();
    return s + (wid ? wsum[wid - 1] : 0);
}

__global__ void k_scan1(int n) {
    int i = blockIdx.x * 1024 + threadIdx.x;
    int v = (i < n) ? g_cnt[i] : 0;
    int incl = block_scan_incl(v);
    if (i < n) g_off[i + 1] = incl;
    if (threadIdx.x == 1023) g_bsum[blockIdx.x] = incl;
}

// scan3 computes its own block prefix (warp reduction over <=49 block sums)
__global__ void k_scan3(int n) {
    __shared__ int pre;
    if (threadIdx.x < 32) {
        int s = 0;
        for (int j = threadIdx.x; j < (int)blockIdx.x; j += 32) s += g_bsum[j];
        #pragma unroll
        for (int d = 16; d; d >>= 1) s += __shfl_down_sync(0xFFFFFFFFu, s, d);
        if (threadIdx.x == 0) pre = s;
    }
    __syncthreads();
    int i = blockIdx.x * 1024 + threadIdx.x;
    if (i < n) {
        int off = g_off[i + 1] + pre;
        g_off[i + 1] = off;
        g_cur[i]     = off - g_cnt[i];
    }
    if (i == 0) g_off[0] = 0;
}

__global__ void k_scatter(const int* __restrict__ src, const int* __restrict__ tgt,
                          const float* __restrict__ ea, int E) {
    int i = blockIdx.x * blockDim.x + threadIdx.x;
    if (i < E) {
        int p = atomicAdd(&g_cur[tgt[i]], 1);
        g_edge[p] = make_int2(src[i], __float_as_int(ea[i]));
    }
}

// ---------------- aggregation: one warp per node (fp16 gather, fp32 residual) ----
__global__ void k_agg(const __half* __restrict__ hf, const float* __restrict__ h,
                      const float* __restrict__ lw, const float* __restrict__ lb,
                      const float* __restrict__ eps, int l,
                      float* __restrict__ out, int n) {
    int warp = (blockIdx.x * blockDim.x + threadIdx.x) >> 5;
    int lane = threadIdx.x & 31;
    if (warp >= n) return;
    int s0 = g_off[warp], s1 = g_off[warp + 1];
    float4 lw4 = *(const float4*)(lw + lane * 4);
    float4 lb4 = *(const float4*)(lb + lane * 4);
    float4 acc = make_float4(0.f, 0.f, 0.f, 0.f);
    #pragma unroll 4
    for (int e = s0; e < s1; ++e) {
        int2  p = g_edge[e];
        float a = __int_as_float(p.y);
        uint2 u = *(const uint2*)(hf + (size_t)p.x * D + lane * 4);
        float2 f01 = __half22float2(*(__half2*)&u.x);
        float2 f23 = __half22float2(*(__half2*)&u.y);
        acc.x += fmaxf(fmaf(a, lw4.x, lb4.x) + f01.x, 0.f);
        acc.y += fmaxf(fmaf(a, lw4.y, lb4.y) + f01.y, 0.f);
        acc.z += fmaxf(fmaf(a, lw4.z, lb4.z) + f23.x, 0.f);
        acc.w += fmaxf(fmaf(a, lw4.w, lb4.w) + f23.y, 0.f);
    }
    float inv = 1.f / (float)(s1 - s0);
    float g   = 1.f + eps[l];
    float4 hn = *(const float4*)(h + (size_t)warp * D + lane * 4);   // fp32 residual
    float4 o;
    o.x = acc.x * inv + g * hn.x;
    o.y = acc.y * inv + g * hn.y;
    o.z = acc.z * inv + g * hn.z;
    o.w = acc.w * inv + g * hn.w;
    *(float4*)(out + (size_t)warp * D + lane * 4) = o;
}

// ---------------- weight prep (also zeroes g_cnt): transpose + bf16 split ------
__global__ void k_wprep(const float* __restrict__ w1, const float* __restrict__ w2,
                        const float* __restrict__ fw, int n) {
    int idx = blockIdx.x * blockDim.x + threadIdx.x;     // 40 * 128 * 32 = 163840
    if (idx < n) g_cnt[idx] = 0;
    if (idx >= 40 * 128 * 32) return;
    int ch  = idx >> 12;
    int rem = idx & 4095;
    int nn  = rem >> 5;
    int kk  = rem & 31;
    const float* W;
    int kg;
    if (ch < 24) {
        int g  = ch >> 2;
        int cw = ch & 3;
        int layer = g >> 1;
        W  = (g & 1) ? (w2 + (size_t)layer * D * D) : (w1 + (size_t)layer * D * D);
        kg = cw * 32 + kk;
    } else {
        int cw = ch - 24;
        W  = fw;
        kg = cw * 32 + kk;
    }
    float v = W[(size_t)kg * 128 + nn];
    __nv_bfloat16 hi = __float2bfloat16(v);
    __nv_bfloat16 lo = __float2bfloat16(v - __bfloat162float(hi));
    g_wb[ch][nn * 72 + kk]      = hi;
    g_wb[ch][nn * 72 + 32 + kk] = lo;
}

// ---------------- HMMA / LDSM / cp.async helpers ----------------
__device__ __forceinline__ void mma_bf16(float* c, const uint32_t* a, uint32_t b0, uint32_t b1) {
    asm volatile(
        "mma.sync.aligned.m16n8k16.row.col.f32.bf16.bf16.f32 "
        "{%0,%1,%2,%3}, {%4,%5,%6,%7}, {%8,%9}, {%0,%1,%2,%3};"
        : "+f"(c[0]), "+f"(c[1]), "+f"(c[2]), "+f"(c[3])
        : "r"(a[0]), "r"(a[1]), "r"(a[2]), "r"(a[3]), "r"(b0), "r"(b1));
}

__device__ __forceinline__ void ldsm_x4(uint32_t* r, uint32_t addr) {
    asm volatile("ldmatrix.sync.aligned.m8n8.x4.shared.b16 {%0,%1,%2,%3}, [%4];"
                 : "=r"(r[0]), "=r"(r[1]), "=r"(r[2]), "=r"(r[3]) : "r"(addr));
}

__device__ __forceinline__ void cpasync16(uint32_t saddr, const void* gaddr) {
    asm volatile("cp.async.cg.shared.global [%0], [%1], 16;" :: "r"(saddr), "l"(gaddr));
}
__device__ __forceinline__ void cpasync_commit() { asm volatile("cp.async.commit_group;" ::: "memory"); }
__device__ __forceinline__ void cpasync_wait0()  { asm volatile("cp.async.wait_group 0;" ::: "memory"); }

__device__ __forceinline__ void split_bf16(float v, __nv_bfloat16& hi, __nv_bfloat16& lo) {
    hi = __float2bfloat16(v);
    lo = __float2bfloat16(v - __bfloat162float(hi));
}

// stage one 18432B weight chunk (1152 x 16B) via cp.async
__device__ __forceinline__ void stageB_async(uint32_t sbase, const __nv_bfloat16* src, int tid) {
    #pragma unroll
    for (int i = 0; i < 5; ++i) {
        int t = tid + 256 * i;
        if (t < 1152) cpasync16(sbase + t * 16, (const char*)src + t * 16);
    }
}

__device__ __forceinline__ void pack8(const float* v, uint4& hiq, uint4& loq) {
    uint32_t hw[4], lw_[4];
    #pragma unroll
    for (int q = 0; q < 4; ++q) {
        __nv_bfloat16 h0, l0, h1, l1;
        split_bf16(v[q * 2],     h0, l0);
        split_bf16(v[q * 2 + 1], h1, l1);
        __nv_bfloat162 hp = {h0, h1}, lp = {l0, l1};
        hw[q]  = *(uint32_t*)&hp;
        lw_[q] = *(uint32_t*)&lp;
    }
    hiq = *(uint4*)hw;
    loq = *(uint4*)lw_;
}

#define SB_BUF_BYTES 18432
#define SA_LAYER_BYTES 9216
#define SMID_BYTES 33792

// ---------------- fused layer MLP: h = relu(A@w1+b1)@w2+b2 ----------------
// 64x128 tile / 256 threads. KB=32 pipelined: cp.async B + reg-prefetch A, double buffers.
// w2 chunk 0 prefetched during phase-1's last chunk. Epilogue 2 also writes fp16 shadow.
__global__ void __launch_bounds__(256) k_layer_mlp(
    const float* __restrict__ A, int wb1, int wb2,
    const float* __restrict__ bias1, const float* __restrict__ bias2,
    float* __restrict__ Cout, __half* __restrict__ HFout, int M)
{
    extern __shared__ __align__(16) char dyn[];
    __nv_bfloat16* sU = (__nv_bfloat16*)dyn;                       // sMid / phase-1 sA double buf
    __nv_bfloat16* sB = (__nv_bfloat16*)(dyn + SMID_BYTES);        // 2 x weight chunk

    const int tid  = threadIdx.x;
    const int w    = tid >> 5;
    const int lane = tid & 31;
    const int wr   = w & 1;
    const int wc   = w >> 1;
    const int gid  = lane >> 2;
    const int tg   = lane & 3;
    const int lg   = lane >> 3;
    const int lr   = lane & 7;
    const int brow = blockIdx.x * 64;

    const uint32_t sUb = (uint32_t)__cvta_generic_to_shared(sU);
    const uint32_t sBb = (uint32_t)__cvta_generic_to_shared(sB);

    const int a_row_off = (lg & 1) * 8 + lr;
    const int a_k_off   = (lg >> 1) * 8;
    const int b_n_off   = (lg >> 1) * 8 + lr;
    const int b_k_off   = (lg & 1) * 8;

    float c[2][4][4];
    #pragma unroll
    for (int mt = 0; mt < 2; ++mt)
        #pragma unroll
        for (int nt = 0; nt < 4; ++nt)
            #pragma unroll
            for (int j = 0; j < 4; ++j) c[mt][nt][j] = 0.f;

    const int arow = tid >> 2;       // 0..63
    const int aq   = (tid & 3) * 8;  // 8 fp32 each
    const int grow = brow + arow;

    float v[8];
    // ---------- prologue: stage chunk 0 ----------
    stageB_async(sBb, g_wb[wb1], tid);
    cpasync_commit();
    if (grow < M) {
        float4 f0 = *(const float4*)(A + (size_t)grow * D + aq);
        float4 f1 = *(const float4*)(A + (size_t)grow * D + aq + 4);
        v[0]=f0.x; v[1]=f0.y; v[2]=f0.z; v[3]=f0.w; v[4]=f1.x; v[5]=f1.y; v[6]=f1.z; v[7]=f1.w;
    } else {
        #pragma unroll
        for (int i = 0; i < 8; ++i) v[i] = 0.f;
    }
    {
        uint4 hiq, loq; pack8(v, hiq, loq);
        *(uint4*)&sU[arow * 72 + aq]      = hiq;
        *(uint4*)&sU[arow * 72 + 32 + aq] = loq;
    }
    cpasync_wait0();
    __syncthreads();

    // ================= phase 1: mid = A @ w1 (4 chunks, pipelined) ============
    int buf = 0;
    for (int ch = 0; ch < 4; ++ch) {
        const bool more = (ch < 3);
        stageB_async(sBb + (buf ^ 1) * SB_BUF_BYTES,
                     more ? g_wb[wb1 + ch + 1] : g_wb[wb2], tid);
        cpasync_commit();
        if (more && grow < M) {
            const float* ap = A + (size_t)grow * D + (ch + 1) * 32 + aq;
            float4 f0 = *(const float4*)(ap);
            float4 f1 = *(const float4*)(ap + 4);
            v[0]=f0.x; v[1]=f0.y; v[2]=f0.z; v[3]=f0.w; v[4]=f1.x; v[5]=f1.y; v[6]=f1.z; v[7]=f1.w;
        }
        const uint32_t aB = sUb + buf * SA_LAYER_BYTES;
        const uint32_t bB = sBb + buf * SB_BUF_BYTES;
        #pragma unroll
        for (int ks = 0; ks < 2; ++ks) {
            #pragma unroll
            for (int p = 0; p < 3; ++p) {
                const int ak = ((p == 1) ? 32 : 0) + ks * 16;
                const int bk = ((p == 2) ? 32 : 0) + ks * 16;
                uint32_t a[2][4], b[2][4];
                #pragma unroll
                for (int mt = 0; mt < 2; ++mt)
                    ldsm_x4(a[mt], aB + ((wr * 32 + mt * 16 + a_row_off) * 72 + ak + a_k_off) * 2);
                #pragma unroll
                for (int np = 0; np < 2; ++np)
                    ldsm_x4(b[np], bB + ((wc * 32 + np * 16 + b_n_off) * 72 + bk + b_k_off) * 2);
                #pragma unroll
                for (int np = 0; np < 2; ++np) {
                    mma_bf16(c[0][np * 2],     a[0], b[np][0], b[np][1]);
                    mma_bf16(c[1][np * 2],     a[1], b[np][0], b[np][1]);
                    mma_bf16(c[0][np * 2 + 1], a[0], b[np][2], b[np][3]);
                    mma_bf16(c[1][np * 2 + 1], a[1], b[np][2], b[np][3]);
                }
            }
        }
        if (more) {
            uint4 hiq, loq; pack8(v, hiq, loq);
            __nv_bfloat16* sA1 = sU + (buf ^ 1) * (SA_LAYER_BYTES / 2);
            *(uint4*)&sA1[arow * 72 + aq]      = hiq;
            *(uint4*)&sA1[arow * 72 + 32 + aq] = loq;
        }
        cpasync_wait0();
        __syncthreads();
        buf ^= 1;
    }
    // buf now points at the staged w2 chunk 0.

    // ============ epilogue 1: bias + relu + bf16 split -> sMid ============
    float c2[2][4][4];
    #pragma unroll
    for (int mt = 0; mt < 2; ++mt) {
        #pragma unroll
        for (int nt = 0; nt < 4; ++nt) {
            int col = wc * 32 + nt * 8 + tg * 2;
            float bx = bias1[col], by = bias1[col + 1];
            #pragma unroll
            for (int half = 0; half < 2; ++half) {
                int r = wr * 32 + mt * 16 + gid + half * 8;
                float v0 = fmaxf(c[mt][nt][half * 2]     + bx, 0.f);
                float v1 = fmaxf(c[mt][nt][half * 2 + 1] + by, 0.f);
                __nv_bfloat16 h0, l0, h1, l1;
                split_bf16(v0, h0, l0);
                split_bf16(v1, h1, l1);
                __nv_bfloat162 hp = {h0, h1}, lp = {l0, l1};
                *(uint32_t*)&sU[r * 264 + col]       = *(uint32_t*)&hp;
                *(uint32_t*)&sU[r * 264 + 128 + col] = *(uint32_t*)&lp;
            }
            #pragma unroll
            for (int j = 0; j < 4; ++j) c2[mt][nt][j] = 0.f;
        }
    }
    __syncthreads();

    // ================= phase 2: h = mid @ w2 (4 chunks; buf holds w2[0]) ============
    for (int ch = 0; ch < 4; ++ch) {
        if (ch < 3) {
            stageB_async(sBb + (buf ^ 1) * SB_BUF_BYTES, g_wb[wb2 + ch + 1], tid);
            cpasync_commit();
        }
        const uint32_t bB = sBb + buf * SB_BUF_BYTES;
        #pragma unroll
        for (int ks = 0; ks < 2; ++ks) {
            #pragma unroll
            for (int p = 0; p < 3; ++p) {
                const int ak = ch * 32 + ks * 16 + ((p == 1) ? 128 : 0);
                const int bk = ((p == 2) ? 32 : 0) + ks * 16;
                uint32_t a[2][4], b[2][4];
                #pragma unroll
                for (int mt = 0; mt < 2; ++mt)
                    ldsm_x4(a[mt], sUb + ((wr * 32 + mt * 16 + a_row_off) * 264 + ak + a_k_off) * 2);
                #pragma unroll
                for (int np = 0; np < 2; ++np)
                    ldsm_x4(b[np], bB + ((wc * 32 + np * 16 + b_n_off) * 72 + bk + b_k_off) * 2);
                #pragma unroll
                for (int np = 0; np < 2; ++np) {
                    mma_bf16(c2[0][np * 2],     a[0], b[np][0], b[np][1]);
                    mma_bf16(c2[1][np * 2],     a[1], b[np][0], b[np][1]);
                    mma_bf16(c2[0][np * 2 + 1], a[0], b[np][2], b[np][3]);
                    mma_bf16(c2[1][np * 2 + 1], a[1], b[np][2], b[np][3]);
                }
            }
        }
        if (ch < 3) {
            cpasync_wait0();
            __syncthreads();
        }
        buf ^= 1;
    }

    // ============ epilogue 2: bias2 -> global (fp32 + optional fp16 shadow) ============
    #pragma unroll
    for (int mt = 0; mt < 2; ++mt) {
        #pragma unroll
        for (int nt = 0; nt < 4; ++nt) {
            int col = wc * 32 + nt * 8 + tg * 2;
            float bx = bias2[col], by = bias2[col + 1];
            int r0 = brow + wr * 32 + mt * 16 + gid;
            float v0 = c2[mt][nt][0] + bx, v1 = c2[mt][nt][1] + by;
            float v2 = c2[mt][nt][2] + bx, v3 = c2[mt][nt][3] + by;
            if (r0 < M) {
                *(float2*)(Cout + (size_t)r0 * D + col) = make_float2(v0, v1);
                if (HFout) {
                    __half2 hp = __float22half2_rn(make_float2(v0, v1));
                    *(uint32_t*)(HFout + (size_t)r0 * D + col) = *(uint32_t*)&hp;
                }
            }
            if (r0 + 8 < M) {
                *(float2*)(Cout + (size_t)(r0 + 8) * D + col) = make_float2(v2, v3);
                if (HFout) {
                    __half2 hp = __float22half2_rn(make_float2(v2, v3));
                    *(uint32_t*)(HFout + (size_t)(r0 + 8) * D + col) = *(uint32_t*)&hp;
                }
            }
        }
    }
}

// ---------------- final GEMM: C = concat(A0..A3) @ W + bias (pipelined) ----
__global__ void __launch_bounds__(256) k_gemm_final(
    const float* __restrict__ A0, const float* __restrict__ A1,
    const float* __restrict__ A2, const float* __restrict__ A3,
    int wbase, const float* __restrict__ bias, float* __restrict__ C, int M)
{
    extern __shared__ __align__(16) char dyn[];
    __nv_bfloat16* sA = (__nv_bfloat16*)dyn;                        // 2 x 128*72
    __nv_bfloat16* sB = (__nv_bfloat16*)(dyn + 2 * SB_BUF_BYTES);   // 2 x 128*72

    const int tid  = threadIdx.x;
    const int w    = tid >> 5;
    const int lane = tid & 31;
    const int wr   = w & 3;
    const int wc   = w >> 2;
    const int gid  = lane >> 2;
    const int tg   = lane & 3;
    const int lg   = lane >> 3;
    const int lr   = lane & 7;
    const int brow = blockIdx.x * 128;

    const uint32_t sAb = (uint32_t)__cvta_generic_to_shared(sA);
    const uint32_t sBb = (uint32_t)__cvta_generic_to_shared(sB);

    const int a_row_off = (lg & 1) * 8 + lr;
    const int a_k_off   = (lg >> 1) * 8;
    const int b_n_off   = (lg >> 1) * 8 + lr;
    const int b_k_off   = (lg & 1) * 8;

    const float* srcs[4] = {A0, A1, A2, A3};

    float c[2][8][4];
    #pragma unroll
    for (int mt = 0; mt < 2; ++mt)
        #pragma unroll
        for (int nt = 0; nt < 8; ++nt)
            #pragma unroll
            for (int j = 0; j < 4; ++j) c[mt][nt][j] = 0.f;

    const int arow = tid >> 1;          // 0..127
    const int aq   = (tid & 1) * 16;    // 16 fp32 each
    const int grow = brow + arow;

    float v[16];
    auto loadA = [&](int ch) {
        if (grow < M) {
            const float* ap = srcs[ch >> 2] + (size_t)grow * D + (ch & 3) * 32 + aq;
            #pragma unroll
            for (int i = 0; i < 4; ++i) {
                float4 f = *(const float4*)(ap + i * 4);
                v[i * 4 + 0] = f.x; v[i * 4 + 1] = f.y; v[i * 4 + 2] = f.z; v[i * 4 + 3] = f.w;
            }
        } else {
            #pragma unroll
            for (int i = 0; i < 16; ++i) v[i] = 0.f;
        }
    };
    auto storeA = [&](int b) {
        __nv_bfloat16* dst = sA + b * (SB_BUF_BYTES / 2);
        uint4 hiq, loq;
        pack8(v, hiq, loq);
        *(uint4*)&dst[arow * 72 + aq]      = hiq;
        *(uint4*)&dst[arow * 72 + 32 + aq] = loq;
        pack8(v + 8, hiq, loq);
        *(uint4*)&dst[arow * 72 + aq + 8]      = hiq;
        *(uint4*)&dst[arow * 72 + 32 + aq + 8] = loq;
    };

    // ---------- prologue ----------
    stageB_async(sBb, g_wb[wbase], tid);
    cpasync_commit();
    loadA(0);
    storeA(0);
    cpasync_wait0();
    __syncthreads();

    int buf = 0;
    for (int ch = 0; ch < 16; ++ch) {
        const bool more = (ch < 15);
        if (more) {
            stageB_async(sBb + (buf ^ 1) * SB_BUF_BYTES, g_wb[wbase + ch + 1], tid);
            cpasync_commit();
            loadA(ch + 1);
        }
        const uint32_t aB = sAb + buf * SB_BUF_BYTES;
        const uint32_t bB = sBb + buf * SB_BUF_BYTES;
        #pragma unroll
        for (int ks = 0; ks < 2; ++ks) {
            #pragma unroll
            for (int p = 0; p < 3; ++p) {
                const int ak = ((p == 1) ? 32 : 0) + ks * 16;
                const int bk = ((p == 2) ? 32 : 0) + ks * 16;
                uint32_t a[2][4], b[4][4];
                #pragma unroll
                for (int mt = 0; mt < 2; ++mt)
                    ldsm_x4(a[mt], aB + ((wr * 32 + mt * 16 + a_row_off) * 72 + ak + a_k_off) * 2);
                #pragma unroll
                for (int np = 0; np < 4; ++np)
                    ldsm_x4(b[np], bB + ((wc * 64 + np * 16 + b_n_off) * 72 + bk + b_k_off) * 2);
                #pragma unroll
                for (int np = 0; np < 4; ++np) {
                    mma_bf16(c[0][np * 2],     a[0], b[np][0], b[np][1]);
                    mma_bf16(c[1][np * 2],     a[1], b[np][0], b[np][1]);
                    mma_bf16(c[0][np * 2 + 1], a[0], b[np][2], b[np][3]);
                    mma_bf16(c[1][np * 2 + 1], a[1], b[np][2], b[np][3]);
                }
            }
        }
        if (more) storeA(buf ^ 1);
        cpasync_wait0();
        __syncthreads();
        buf ^= 1;
    }

    #pragma unroll
    for (int mt = 0; mt < 2; ++mt) {
        #pragma unroll
        for (int nt = 0; nt < 8; ++nt) {
            int col  = wc * 64 + nt * 8 + tg * 2;
            float bx = bias[col], by = bias[col + 1];
            int r0 = brow + wr * 32 + mt * 16 + gid;
            float v0 = c[mt][nt][0] + bx, v1 = c[mt][nt][1] + by;
            float v2 = c[mt][nt][2] + bx, v3 = c[mt][nt][3] + by;
            if (r0 < M)     *(float2*)(C + (size_t)r0 * D + col)       = make_float2(v0, v1);
            if (r0 + 8 < M) *(float2*)(C + (size_t)(r0 + 8) * D + col) = make_float2(v2, v3);
        }
    }
}

// ---------------- launcher ----------------
extern "C" void kernel_launch(void* const* d_in, const int* in_sizes, int n_in,
                              void* d_out, int out_size) {
    const float* x   = (const float*)d_in[0];
    const int*   ei  = (const int*)  d_in[1];
    const float* ea  = (const float*)d_in[2];
    const float* lw  = (const float*)d_in[3];
    const float* lb  = (const float*)d_in[4];
    const float* eps = (const float*)d_in[5];
    const float* w1  = (const float*)d_in[6];
    const float* b1  = (const float*)d_in[7];
    const float* w2  = (const float*)d_in[8];
    const float* b2  = (const float*)d_in[9];
    const float* fw  = (const float*)d_in[10];
    const float* fb  = (const float*)d_in[11];
    float* out = (float*)d_out;

    const int N = in_sizes[0] / D;
    const int E = in_sizes[2];

    const int MLP_SMEM   = SMID_BYTES + 2 * SB_BUF_BYTES;   // 70656
    const int FINAL_SMEM = 4 * SB_BUF_BYTES;                // 73728
    cudaFuncSetAttribute(k_layer_mlp,  cudaFuncAttributeMaxDynamicSharedMemorySize, MLP_SMEM);
    cudaFuncSetAttribute(k_gemm_final, cudaFuncAttributeMaxDynamicSharedMemorySize, FINAL_SMEM);

    float *hbuf, *tmp;
    __half* hfbuf;
    cudaGetSymbolAddress((void**)&hbuf,  g_h);
    cudaGetSymbolAddress((void**)&tmp,   g_tmp);
    cudaGetSymbolAddress((void**)&hfbuf, g_hf);

    // weight prep (also zeroes g_cnt) + CSR build (+ x->fp16 inside hist)
    k_wprep<<<(40 * 128 * 32 + 255) / 256, 256>>>(w1, w2, fw, N);
    k_hist<<<(E + 255) / 256, 256>>>(ei + E, E, x, N * D / 4);
    const int nb = (N + 1023) / 1024;
    k_scan1<<<nb, 1024>>>(N);
    k_scan3<<<nb, 1024>>>(N);
    k_scatter<<<(E + 255) / 256, 256>>>(ei, ei + E, ea, E);

    const float* h = x;
    for (int l = 0; l < 3; ++l) {
        float*  hl  = hbuf  + (size_t)l * NMAX * D;
        __half* hfl = (l < 2) ? (hfbuf + (size_t)(l + 1) * NMAX * D) : (__half*)nullptr;
        const __half* hfsrc = hfbuf + (size_t)l * NMAX * D;
        k_agg<<<(N + 7) / 8, 256>>>(hfsrc, h, lw + l * D, lb + l * D, eps, l, tmp, N);
        k_layer_mlp<<<(N + 63) / 64, 256, MLP_SMEM>>>(tmp, (l * 2 + 0) * 4, (l * 2 + 1) * 4,
                                                      b1 + l * D, b2 + l * D, hl, hfl, N);
        h = hl;
    }

    // final: [x | h1 | h2 | h3] @ fw + fb
    k_gemm_final<<<(N + 127) / 128, 256, FINAL_SMEM>>>(x, hbuf, hbuf + (size_t)NMAX * D,
                                                       hbuf + (size_t)2 * NMAX * D, 24, fb, out, N);
}

// round 12
// speedup vs baseline: 1.0113x; 1.0113x over previous
#include <cuda_runtime.h>
#include <cuda_bf16.h>
#include <cstdint>

#define NMAX 50000
#define EMAX 800000
#define D 128
#define CSR_NB 64

// ---------------- device scratch (no allocations allowed) ----------------
__device__ int      g_cnt[NMAX];
__device__ int      g_off[NMAX + 1];
__device__ int      g_cur[NMAX];
__device__ int2     g_edge[EMAX];       // {src, attr-bits}
__device__ int      g_bsum[64];
__device__ unsigned g_barctr = 0;       // monotonic grid-barrier counter
__device__ float    g_h[3][NMAX * D];   // h1, h2, h3
__device__ float    g_tmp[NMAX * D];
// prepacked weight chunks: 40 chunks (6 layer-GEMMs x 4 + final x 16), KB=32.
// chunk = 128 n-rows x 72 bf16 (k 0..31 = hi, 32..63 = lo, 64..71 pad).
__device__ __align__(16) __nv_bfloat16 g_wb[40][128 * 72];

// ---------------- grid barrier (all CSR_NB blocks resident; monotonic counter) ----
__device__ __forceinline__ void grid_bar() {
    __syncthreads();
    if (threadIdx.x == 0) {
        __threadfence();
        unsigned arrival = atomicAdd(&g_barctr, 1) + 1;
        unsigned target  = ((arrival + CSR_NB - 1) / CSR_NB) * CSR_NB;
        while (atomicAdd(&g_barctr, 0u) < target) {}
        __threadfence();
    }
    __syncthreads();
}

__device__ __forceinline__ int block_scan_incl(int v) {
    __shared__ int wsum[32];
    const int lane = threadIdx.x & 31;
    const int wid  = threadIdx.x >> 5;
    int s = v;
    #pragma unroll
    for (int d = 1; d < 32; d <<= 1) {
        int t = __shfl_up_sync(0xFFFFFFFFu, s, d);
        if (lane >= d) s += t;
    }
    if (lane == 31) wsum[wid] = s;
    __syncthreads();
    if (wid == 0) {
        int ws = wsum[lane];
        #pragma unroll
        for (int d = 1; d < 32; d <<= 1) {
            int t = __shfl_up_sync(0xFFFFFFFFu, ws, d);
            if (lane >= d) ws += t;
        }
        wsum[lane] = ws;
    }
    __syncthreads();
    return s + (wid ? wsum[wid - 1] : 0);
}

// ---------------- fused CSR build: hist -> scan -> scatter, one kernel ----------
__global__ void __launch_bounds__(1024) k_csr(
    const int* __restrict__ src, const int* __restrict__ tgt,
    const float* __restrict__ ea, int E, int n)
{
    const int tid  = threadIdx.x;
    const int bid  = blockIdx.x;
    const int gtid = bid * 1024 + tid;
    const int gsz  = CSR_NB * 1024;

    // phase A: histogram (g_cnt zeroed by k_wprep)
    for (int i = gtid; i < E; i += gsz)
        atomicAdd(&g_cnt[tgt[i]], 1);
    grid_bar();

    // phase B1: block-local inclusive scan
    const int nb = (n + 1023) / 1024;
    if (bid < nb) {
        int i = bid * 1024 + tid;
        int v = (i < n) ? g_cnt[i] : 0;
        int incl = block_scan_incl(v);
        if (i < n) g_off[i + 1] = incl;
        if (tid == 1023) g_bsum[bid] = incl;
    }
    grid_bar();

    // phase B2: add block prefix, derive cursors
    if (bid < nb) {
        __shared__ int pre;
        if (tid < 32) {
            int s = 0;
            for (int j = tid; j < bid; j += 32) s += g_bsum[j];
            #pragma unroll
            for (int d = 16; d; d >>= 1) s += __shfl_down_sync(0xFFFFFFFFu, s, d);
            if (tid == 0) pre = s;
        }
        __syncthreads();
        int i = bid * 1024 + tid;
        if (i < n) {
            int off = g_off[i + 1] + pre;
            g_off[i + 1] = off;
            g_cur[i]     = off - g_cnt[i];
        }
        if (i == 0) g_off[0] = 0;
    }
    grid_bar();

    // phase C: scatter
    for (int i = gtid; i < E; i += gsz) {
        int p = atomicAdd(&g_cur[tgt[i]], 1);
        g_edge[p] = make_int2(src[i], __float_as_int(ea[i]));
    }
}

// ---------------- aggregation: one warp per node (fp32 gather) ----------------
__global__ void k_agg(const float* __restrict__ h,
                      const float* __restrict__ lw, const float* __restrict__ lb,
                      const float* __restrict__ eps, int l,
                      float* __restrict__ out, int n) {
    int warp = (blockIdx.x * blockDim.x + threadIdx.x) >> 5;
    int lane = threadIdx.x & 31;
    if (warp >= n) return;
    int s0 = g_off[warp], s1 = g_off[warp + 1];
    float4 lw4 = *(const float4*)(lw + lane * 4);
    float4 lb4 = *(const float4*)(lb + lane * 4);
    float4 acc = make_float4(0.f, 0.f, 0.f, 0.f);
    #pragma unroll 4
    for (int e = s0; e < s1; ++e) {
        int2  p = g_edge[e];
        float a = __int_as_float(p.y);
        float4 hv = *(const float4*)(h + (size_t)p.x * D + lane * 4);
        acc.x += fmaxf(fmaf(a, lw4.x, lb4.x) + hv.x, 0.f);
        acc.y += fmaxf(fmaf(a, lw4.y, lb4.y) + hv.y, 0.f);
        acc.z += fmaxf(fmaf(a, lw4.z, lb4.z) + hv.z, 0.f);
        acc.w += fmaxf(fmaf(a, lw4.w, lb4.w) + hv.w, 0.f);
    }
    float inv = 1.f / (float)(s1 - s0);
    float g   = 1.f + eps[l];
    float4 hn = *(const float4*)(h + (size_t)warp * D + lane * 4);
    float4 o;
    o.x = acc.x * inv + g * hn.x;
    o.y = acc.y * inv + g * hn.y;
    o.z = acc.z * inv + g * hn.z;
    o.w = acc.w * inv + g * hn.w;
    *(float4*)(out + (size_t)warp * D + lane * 4) = o;
}

// ---------------- weight prep (also zeroes g_cnt): transpose + bf16 split ------
__global__ void k_wprep(const float* __restrict__ w1, const float* __restrict__ w2,
                        const float* __restrict__ fw, int n) {
    int idx = blockIdx.x * blockDim.x + threadIdx.x;     // 40 * 128 * 32 = 163840
    if (idx < n) g_cnt[idx] = 0;
    if (idx >= 40 * 128 * 32) return;
    int ch  = idx >> 12;
    int rem = idx & 4095;
    int nn  = rem >> 5;
    int kk  = rem & 31;
    const float* W;
    int kg;
    if (ch < 24) {
        int g  = ch >> 2;
        int cw = ch & 3;
        int layer = g >> 1;
        W  = (g & 1) ? (w2 + (size_t)layer * D * D) : (w1 + (size_t)layer * D * D);
        kg = cw * 32 + kk;
    } else {
        int cw = ch - 24;
        W  = fw;
        kg = cw * 32 + kk;
    }
    float v = W[(size_t)kg * 128 + nn];
    __nv_bfloat16 hi = __float2bfloat16(v);
    __nv_bfloat16 lo = __float2bfloat16(v - __bfloat162float(hi));
    g_wb[ch][nn * 72 + kk]      = hi;
    g_wb[ch][nn * 72 + 32 + kk] = lo;
}

// ---------------- HMMA / LDSM / cp.async helpers ----------------
__device__ __forceinline__ void mma_bf16(float* c, const uint32_t* a, uint32_t b0, uint32_t b1) {
    asm volatile(
        "mma.sync.aligned.m16n8k16.row.col.f32.bf16.bf16.f32 "
        "{%0,%1,%2,%3}, {%4,%5,%6,%7}, {%8,%9}, {%0,%1,%2,%3};"
        : "+f"(c[0]), "+f"(c[1]), "+f"(c[2]), "+f"(c[3])
        : "r"(a[0]), "r"(a[1]), "r"(a[2]), "r"(a[3]), "r"(b0), "r"(b1));
}

__device__ __forceinline__ void ldsm_x4(uint32_t* r, uint32_t addr) {
    asm volatile("ldmatrix.sync.aligned.m8n8.x4.shared.b16 {%0,%1,%2,%3}, [%4];"
                 : "=r"(r[0]), "=r"(r[1]), "=r"(r[2]), "=r"(r[3]) : "r"(addr));
}

__device__ __forceinline__ void cpasync16(uint32_t saddr, const void* gaddr) {
    asm volatile("cp.async.cg.shared.global [%0], [%1], 16;" :: "r"(saddr), "l"(gaddr));
}
__device__ __forceinline__ void cpasync_commit() { asm volatile("cp.async.commit_group;" ::: "memory"); }
__device__ __forceinline__ void cpasync_wait0()  { asm volatile("cp.async.wait_group 0;" ::: "memory"); }

__device__ __forceinline__ void split_bf16(float v, __nv_bfloat16& hi, __nv_bfloat16& lo) {
    hi = __float2bfloat16(v);
    lo = __float2bfloat16(v - __bfloat162float(hi));
}

// stage one 18432B weight chunk (1152 x 16B) via cp.async
__device__ __forceinline__ void stageB_async(uint32_t sbase, const __nv_bfloat16* src, int tid) {
    #pragma unroll
    for (int i = 0; i < 5; ++i) {
        int t = tid + 256 * i;
        if (t < 1152) cpasync16(sbase + t * 16, (const char*)src + t * 16);
    }
}

__device__ __forceinline__ void pack8(const float* v, uint4& hiq, uint4& loq) {
    uint32_t hw[4], lw_[4];
    #pragma unroll
    for (int q = 0; q < 4; ++q) {
        __nv_bfloat16 h0, l0, h1, l1;
        split_bf16(v[q * 2],     h0, l0);
        split_bf16(v[q * 2 + 1], h1, l1);
        __nv_bfloat162 hp = {h0, h1}, lp = {l0, l1};
        hw[q]  = *(uint32_t*)&hp;
        lw_[q] = *(uint32_t*)&lp;
    }
    hiq = *(uint4*)hw;
    loq = *(uint4*)lw_;
}

#define SB_BUF_BYTES 18432
#define SA_LAYER_BYTES 9216
#define SMID_BYTES 33792

// ---------------- fused layer MLP: h = relu(A@w1+b1)@w2+b2 ----------------
// 64x128 tile / 256 threads. KB=32 pipelined: cp.async B + reg-prefetch A, double buffers.
// w2 chunk 0 prefetched during phase-1's last chunk (no inter-phase bubble).
__global__ void __launch_bounds__(256) k_layer_mlp(
    const float* __restrict__ A, int wb1, int wb2,
    const float* __restrict__ bias1, const float* __restrict__ bias2,
    float* __restrict__ Cout, int M)
{
    extern __shared__ __align__(16) char dyn[];
    __nv_bfloat16* sU = (__nv_bfloat16*)dyn;                       // sMid / phase-1 sA double buf
    __nv_bfloat16* sB = (__nv_bfloat16*)(dyn + SMID_BYTES);        // 2 x weight chunk

    const int tid  = threadIdx.x;
    const int w    = tid >> 5;
    const int lane = tid & 31;
    const int wr   = w & 1;
    const int wc   = w >> 1;
    const int gid  = lane >> 2;
    const int tg   = lane & 3;
    const int lg   = lane >> 3;
    const int lr   = lane & 7;
    const int brow = blockIdx.x * 64;

    const uint32_t sUb = (uint32_t)__cvta_generic_to_shared(sU);
    const uint32_t sBb = (uint32_t)__cvta_generic_to_shared(sB);

    const int a_row_off = (lg & 1) * 8 + lr;
    const int a_k_off   = (lg >> 1) * 8;
    const int b_n_off   = (lg >> 1) * 8 + lr;
    const int b_k_off   = (lg & 1) * 8;

    float c[2][4][4];
    #pragma unroll
    for (int mt = 0; mt < 2; ++mt)
        #pragma unroll
        for (int nt = 0; nt < 4; ++nt)
            #pragma unroll
            for (int j = 0; j < 4; ++j) c[mt][nt][j] = 0.f;

    const int arow = tid >> 2;       // 0..63
    const int aq   = (tid & 3) * 8;  // 8 fp32 each
    const int grow = brow + arow;

    float v[8];
    // ---------- prologue: stage chunk 0 ----------
    stageB_async(sBb, g_wb[wb1], tid);
    cpasync_commit();
    if (grow < M) {
        float4 f0 = *(const float4*)(A + (size_t)grow * D + aq);
        float4 f1 = *(const float4*)(A + (size_t)grow * D + aq + 4);
        v[0]=f0.x; v[1]=f0.y; v[2]=f0.z; v[3]=f0.w; v[4]=f1.x; v[5]=f1.y; v[6]=f1.z; v[7]=f1.w;
    } else {
        #pragma unroll
        for (int i = 0; i < 8; ++i) v[i] = 0.f;
    }
    {
        uint4 hiq, loq; pack8(v, hiq, loq);
        *(uint4*)&sU[arow * 72 + aq]      = hiq;
        *(uint4*)&sU[arow * 72 + 32 + aq] = loq;
    }
    cpasync_wait0();
    __syncthreads();

    // ================= phase 1: mid = A @ w1 (4 chunks, pipelined) ============
    int buf = 0;
    for (int ch = 0; ch < 4; ++ch) {
        const bool more = (ch < 3);
        // prefetch: next w1 chunk, or w2 chunk 0 on the last iteration (no bubble)
        stageB_async(sBb + (buf ^ 1) * SB_BUF_BYTES,
                     more ? g_wb[wb1 + ch + 1] : g_wb[wb2], tid);
        cpasync_commit();
        if (more && grow < M) {
            const float* ap = A + (size_t)grow * D + (ch + 1) * 32 + aq;
            float4 f0 = *(const float4*)(ap);
            float4 f1 = *(const float4*)(ap + 4);
            v[0]=f0.x; v[1]=f0.y; v[2]=f0.z; v[3]=f0.w; v[4]=f1.x; v[5]=f1.y; v[6]=f1.z; v[7]=f1.w;
        }
        const uint32_t aB = sUb + buf * SA_LAYER_BYTES;
        const uint32_t bB = sBb + buf * SB_BUF_BYTES;
        #pragma unroll
        for (int ks = 0; ks < 2; ++ks) {
            #pragma unroll
            for (int p = 0; p < 3; ++p) {
                const int ak = ((p == 1) ? 32 : 0) + ks * 16;
                const int bk = ((p == 2) ? 32 : 0) + ks * 16;
                uint32_t a[2][4], b[2][4];
                #pragma unroll
                for (int mt = 0; mt < 2; ++mt)
                    ldsm_x4(a[mt], aB + ((wr * 32 + mt * 16 + a_row_off) * 72 + ak + a_k_off) * 2);
                #pragma unroll
                for (int np = 0; np < 2; ++np)
                    ldsm_x4(b[np], bB + ((wc * 32 + np * 16 + b_n_off) * 72 + bk + b_k_off) * 2);
                #pragma unroll
                for (int np = 0; np < 2; ++np) {
                    mma_bf16(c[0][np * 2],     a[0], b[np][0], b[np][1]);
                    mma_bf16(c[1][np * 2],     a[1], b[np][0], b[np][1]);
                    mma_bf16(c[0][np * 2 + 1], a[0], b[np][2], b[np][3]);
                    mma_bf16(c[1][np * 2 + 1], a[1], b[np][2], b[np][3]);
                }
            }
        }
        if (more) {
            uint4 hiq, loq; pack8(v, hiq, loq);
            __nv_bfloat16* sA1 = sU + (buf ^ 1) * (SA_LAYER_BYTES / 2);
            *(uint4*)&sA1[arow * 72 + aq]      = hiq;
            *(uint4*)&sA1[arow * 72 + 32 + aq] = loq;
        }
        cpasync_wait0();
        __syncthreads();
        buf ^= 1;
    }
    // buf now points at the staged w2 chunk 0.

    // ============ epilogue 1: bias + relu + bf16 split -> sMid ============
    float c2[2][4][4];
    #pragma unroll
    for (int mt = 0; mt < 2; ++mt) {
        #pragma unroll
        for (int nt = 0; nt < 4; ++nt) {
            int col = wc * 32 + nt * 8 + tg * 2;
            float bx = bias1[col], by = bias1[col + 1];
            #pragma unroll
            for (int half = 0; half < 2; ++half) {
                int r = wr * 32 + mt * 16 + gid + half * 8;
                float v0 = fmaxf(c[mt][nt][half * 2]     + bx, 0.f);
                float v1 = fmaxf(c[mt][nt][half * 2 + 1] + by, 0.f);
                __nv_bfloat16 h0, l0, h1, l1;
                split_bf16(v0, h0, l0);
                split_bf16(v1, h1, l1);
                __nv_bfloat162 hp = {h0, h1}, lp = {l0, l1};
                *(uint32_t*)&sU[r * 264 + col]       = *(uint32_t*)&hp;
                *(uint32_t*)&sU[r * 264 + 128 + col] = *(uint32_t*)&lp;
            }
            #pragma unroll
            for (int j = 0; j < 4; ++j) c2[mt][nt][j] = 0.f;
        }
    }
    __syncthreads();

    // ================= phase 2: h = mid @ w2 (4 chunks; buf holds w2[0]) ============
    for (int ch = 0; ch < 4; ++ch) {
        if (ch < 3) {
            stageB_async(sBb + (buf ^ 1) * SB_BUF_BYTES, g_wb[wb2 + ch + 1], tid);
            cpasync_commit();
        }
        const uint32_t bB = sBb + buf * SB_BUF_BYTES;
        #pragma unroll
        for (int ks = 0; ks < 2; ++ks) {
            #pragma unroll
            for (int p = 0; p < 3; ++p) {
                const int ak = ch * 32 + ks * 16 + ((p == 1) ? 128 : 0);
                const int bk = ((p == 2) ? 32 : 0) + ks * 16;
                uint32_t a[2][4], b[2][4];
                #pragma unroll
                for (int mt = 0; mt < 2; ++mt)
                    ldsm_x4(a[mt], sUb + ((wr * 32 + mt * 16 + a_row_off) * 264 + ak + a_k_off) * 2);
                #pragma unroll
                for (int np = 0; np < 2; ++np)
                    ldsm_x4(b[np], bB + ((wc * 32 + np * 16 + b_n_off) * 72 + bk + b_k_off) * 2);
                #pragma unroll
                for (int np = 0; np < 2; ++np) {
                    mma_bf16(c2[0][np * 2],     a[0], b[np][0], b[np][1]);
                    mma_bf16(c2[1][np * 2],     a[1], b[np][0], b[np][1]);
                    mma_bf16(c2[0][np * 2 + 1], a[0], b[np][2], b[np][3]);
                    mma_bf16(c2[1][np * 2 + 1], a[1], b[np][2], b[np][3]);
                }
            }
        }
        if (ch < 3) {
            cpasync_wait0();
            __syncthreads();
        }
        buf ^= 1;
    }

    // ============ epilogue 2: bias2 -> global ============
    #pragma unroll
    for (int mt = 0; mt < 2; ++mt) {
        #pragma unroll
        for (int nt = 0; nt < 4; ++nt) {
            int col = wc * 32 + nt * 8 + tg * 2;
            float bx = bias2[col], by = bias2[col + 1];
            int r0 = brow + wr * 32 + mt * 16 + gid;
            float v0 = c2[mt][nt][0] + bx, v1 = c2[mt][nt][1] + by;
            float v2 = c2[mt][nt][2] + bx, v3 = c2[mt][nt][3] + by;
            if (r0 < M)     *(float2*)(Cout + (size_t)r0 * D + col)       = make_float2(v0, v1);
            if (r0 + 8 < M) *(float2*)(Cout + (size_t)(r0 + 8) * D + col) = make_float2(v2, v3);
        }
    }
}

// ---------------- final GEMM: C = concat(A0..A3) @ W + bias (pipelined) ----
__global__ void __launch_bounds__(256) k_gemm_final(
    const float* __restrict__ A0, const float* __restrict__ A1,
    const float* __restrict__ A2, const float* __restrict__ A3,
    int wbase, const float* __restrict__ bias, float* __restrict__ C, int M)
{
    extern __shared__ __align__(16) char dyn[];
    __nv_bfloat16* sA = (__nv_bfloat16*)dyn;                        // 2 x 128*72
    __nv_bfloat16* sB = (__nv_bfloat16*)(dyn + 2 * SB_BUF_BYTES);   // 2 x 128*72

    const int tid  = threadIdx.x;
    const int w    = tid >> 5;
    const int lane = tid & 31;
    const int wr   = w & 3;
    const int wc   = w >> 2;
    const int gid  = lane >> 2;
    const int tg   = lane & 3;
    const int lg   = lane >> 3;
    const int lr   = lane & 7;
    const int brow = blockIdx.x * 128;

    const uint32_t sAb = (uint32_t)__cvta_generic_to_shared(sA);
    const uint32_t sBb = (uint32_t)__cvta_generic_to_shared(sB);

    const int a_row_off = (lg & 1) * 8 + lr;
    const int a_k_off   = (lg >> 1) * 8;
    const int b_n_off   = (lg >> 1) * 8 + lr;
    const int b_k_off   = (lg & 1) * 8;

    const float* srcs[4] = {A0, A1, A2, A3};

    float c[2][8][4];
    #pragma unroll
    for (int mt = 0; mt < 2; ++mt)
        #pragma unroll
        for (int nt = 0; nt < 8; ++nt)
            #pragma unroll
            for (int j = 0; j < 4; ++j) c[mt][nt][j] = 0.f;

    const int arow = tid >> 1;          // 0..127
    const int aq   = (tid & 1) * 16;    // 16 fp32 each
    const int grow = brow + arow;

    float v[16];
    auto loadA = [&](int ch) {
        if (grow < M) {
            const float* ap = srcs[ch >> 2] + (size_t)grow * D + (ch & 3) * 32 + aq;
            #pragma unroll
            for (int i = 0; i < 4; ++i) {
                float4 f = *(const float4*)(ap + i * 4);
                v[i * 4 + 0] = f.x; v[i * 4 + 1] = f.y; v[i * 4 + 2] = f.z; v[i * 4 + 3] = f.w;
            }
        } else {
            #pragma unroll
            for (int i = 0; i < 16; ++i) v[i] = 0.f;
        }
    };
    auto storeA = [&](int b) {
        __nv_bfloat16* dst = sA + b * (SB_BUF_BYTES / 2);
        uint4 hiq, loq;
        pack8(v, hiq, loq);
        *(uint4*)&dst[arow * 72 + aq]      = hiq;
        *(uint4*)&dst[arow * 72 + 32 + aq] = loq;
        pack8(v + 8, hiq, loq);
        *(uint4*)&dst[arow * 72 + aq + 8]      = hiq;
        *(uint4*)&dst[arow * 72 + 32 + aq + 8] = loq;
    };

    // ---------- prologue ----------
    stageB_async(sBb, g_wb[wbase], tid);
    cpasync_commit();
    loadA(0);
    storeA(0);
    cpasync_wait0();
    __syncthreads();

    int buf = 0;
    for (int ch = 0; ch < 16; ++ch) {
        const bool more = (ch < 15);
        if (more) {
            stageB_async(sBb + (buf ^ 1) * SB_BUF_BYTES, g_wb[wbase + ch + 1], tid);
            cpasync_commit();
            loadA(ch + 1);
        }
        const uint32_t aB = sAb + buf * SB_BUF_BYTES;
        const uint32_t bB = sBb + buf * SB_BUF_BYTES;
        #pragma unroll
        for (int ks = 0; ks < 2; ++ks) {
            #pragma unroll
            for (int p = 0; p < 3; ++p) {
                const int ak = ((p == 1) ? 32 : 0) + ks * 16;
                const int bk = ((p == 2) ? 32 : 0) + ks * 16;
                uint32_t a[2][4], b[4][4];
                #pragma unroll
                for (int mt = 0; mt < 2; ++mt)
                    ldsm_x4(a[mt], aB + ((wr * 32 + mt * 16 + a_row_off) * 72 + ak + a_k_off) * 2);
                #pragma unroll
                for (int np = 0; np < 4; ++np)
                    ldsm_x4(b[np], bB + ((wc * 64 + np * 16 + b_n_off) * 72 + bk + b_k_off) * 2);
                #pragma unroll
                for (int np = 0; np < 4; ++np) {
                    mma_bf16(c[0][np * 2],     a[0], b[np][0], b[np][1]);
                    mma_bf16(c[1][np * 2],     a[1], b[np][0], b[np][1]);
                    mma_bf16(c[0][np * 2 + 1], a[0], b[np][2], b[np][3]);
                    mma_bf16(c[1][np * 2 + 1], a[1], b[np][2], b[np][3]);
                }
            }
        }
        if (more) storeA(buf ^ 1);
        cpasync_wait0();
        __syncthreads();
        buf ^= 1;
    }

    #pragma unroll
    for (int mt = 0; mt < 2; ++mt) {
        #pragma unroll
        for (int nt = 0; nt < 8; ++nt) {
            int col  = wc * 64 + nt * 8 + tg * 2;
            float bx = bias[col], by = bias[col + 1];
            int r0 = brow + wr * 32 + mt * 16 + gid;
            float v0 = c[mt][nt][0] + bx, v1 = c[mt][nt][1] + by;
            float v2 = c[mt][nt][2] + bx, v3 = c[mt][nt][3] + by;
            if (r0 < M)     *(float2*)(C + (size_t)r0 * D + col)       = make_float2(v0, v1);
            if (r0 + 8 < M) *(float2*)(C + (size_t)(r0 + 8) * D + col) = make_float2(v2, v3);
        }
    }
}

// ---------------- launcher ----------------
extern "C" void kernel_launch(void* const* d_in, const int* in_sizes, int n_in,
                              void* d_out, int out_size) {
    const float* x   = (const float*)d_in[0];
    const int*   ei  = (const int*)  d_in[1];
    const float* ea  = (const float*)d_in[2];
    const float* lw  = (const float*)d_in[3];
    const float* lb  = (const float*)d_in[4];
    const float* eps = (const float*)d_in[5];
    const float* w1  = (const float*)d_in[6];
    const float* b1  = (const float*)d_in[7];
    const float* w2  = (const float*)d_in[8];
    const float* b2  = (const float*)d_in[9];
    const float* fw  = (const float*)d_in[10];
    const float* fb  = (const float*)d_in[11];
    float* out = (float*)d_out;

    const int N = in_sizes[0] / D;
    const int E = in_sizes[2];

    const int MLP_SMEM   = SMID_BYTES + 2 * SB_BUF_BYTES;   // 70656
    const int FINAL_SMEM = 4 * SB_BUF_BYTES;                // 73728
    cudaFuncSetAttribute(k_layer_mlp,  cudaFuncAttributeMaxDynamicSharedMemorySize, MLP_SMEM);
    cudaFuncSetAttribute(k_gemm_final, cudaFuncAttributeMaxDynamicSharedMemorySize, FINAL_SMEM);

    float *hbuf, *tmp;
    cudaGetSymbolAddress((void**)&hbuf, g_h);
    cudaGetSymbolAddress((void**)&tmp,  g_tmp);

    // weight prep (also zeroes g_cnt) + fused CSR build
    k_wprep<<<(40 * 128 * 32 + 255) / 256, 256>>>(w1, w2, fw, N);
    k_csr<<<CSR_NB, 1024>>>(ei, ei + E, ea, E, N);

    const float* h = x;
    for (int l = 0; l < 3; ++l) {
        float* hl = hbuf + (size_t)l * NMAX * D;
        k_agg<<<(N + 7) / 8, 256>>>(h, lw + l * D, lb + l * D, eps, l, tmp, N);
        k_layer_mlp<<<(N + 63) / 64, 256, MLP_SMEM>>>(tmp, (l * 2 + 0) * 4, (l * 2 + 1) * 4,
                                                      b1 + l * D, b2 + l * D, hl, N);
        h = hl;
    }

    // final: [x | h1 | h2 | h3] @ fw + fb
    k_gemm_final<<<(N + 127) / 128, 256, FINAL_SMEM>>>(x, hbuf, hbuf + (size_t)NMAX * D,
                                                       hbuf + (size_t)2 * NMAX * D, 24, fb, out, N);
}

// round 14
// speedup vs baseline: 1.2139x; 1.2003x over previous
#include <cuda_runtime.h>
#include <cuda_fp16.h>
#include <cstdint>

#define NMAX 50000
#define EMAX 800000
#define D 128

// ---------------- device scratch (no allocations allowed) ----------------
__device__ int    g_cnt[NMAX];
__device__ int    g_off[NMAX + 1];
__device__ int    g_cur[NMAX];
__device__ int2   g_edge[EMAX];       // {src, attr-bits}
__device__ int    g_bsum[64];
__device__ float  g_h[3][NMAX * D];   // h1, h2, h3
__device__ float  g_tmp[NMAX * D];
// prepacked fp16 weight chunks: 40 chunks (6 layer-GEMMs x 4 + final x 16), KB=32.
// chunk = 128 n-rows x 40 fp16 (k 0..31 = W in fp16, 32..39 pad). No lo term needed.
__device__ __align__(16) __half g_wb[40][128 * 40];

// ---------------- preprocessing: CSR by target via counting sort ----------------
__global__ void k_hist(const int* __restrict__ tgt, int E) {
    int i = blockIdx.x * blockDim.x + threadIdx.x;
    if (i < E) atomicAdd(&g_cnt[tgt[i]], 1);
}

__device__ __forceinline__ int block_scan_incl(int v) {
    __shared__ int wsum[32];
    const int lane = threadIdx.x & 31;
    const int wid  = threadIdx.x >> 5;
    int s = v;
    #pragma unroll
    for (int d = 1; d < 32; d <<= 1) {
        int t = __shfl_up_sync(0xFFFFFFFFu, s, d);
        if (lane >= d) s += t;
    }
    if (lane == 31) wsum[wid] = s;
    __syncthreads();
    if (wid == 0) {
        int ws = wsum[lane];
        #pragma unroll
        for (int d = 1; d < 32; d <<= 1) {
            int t = __shfl_up_sync(0xFFFFFFFFu, ws, d);
            if (lane >= d) ws += t;
        }
        wsum[lane] = ws;
    }
    __syncthreads();
    return s + (wid ? wsum[wid - 1] : 0);
}

__global__ void k_scan1(int n) {
    int i = blockIdx.x * 1024 + threadIdx.x;
    int v = (i < n) ? g_cnt[i] : 0;
    int incl = block_scan_incl(v);
    if (i < n) g_off[i + 1] = incl;
    if (threadIdx.x == 1023) g_bsum[blockIdx.x] = incl;
}

// scan3 computes its own block prefix (warp reduction over <=49 block sums)
__global__ void k_scan3(int n) {
    __shared__ int pre;
    if (threadIdx.x < 32) {
        int s = 0;
        for (int j = threadIdx.x; j < (int)blockIdx.x; j += 32) s += g_bsum[j];
        #pragma unroll
        for (int d = 16; d; d >>= 1) s += __shfl_down_sync(0xFFFFFFFFu, s, d);
        if (threadIdx.x == 0) pre = s;
    }
    __syncthreads();
    int i = blockIdx.x * 1024 + threadIdx.x;
    if (i < n) {
        int off = g_off[i + 1] + pre;
        g_off[i + 1] = off;
        g_cur[i]     = off - g_cnt[i];
    }
    if (i == 0) g_off[0] = 0;
}

__global__ void k_scatter(const int* __restrict__ src, const int* __restrict__ tgt,
                          const float* __restrict__ ea, int E) {
    int i = blockIdx.x * blockDim.x + threadIdx.x;
    if (i < E) {
        int p = atomicAdd(&g_cur[tgt[i]], 1);
        g_edge[p] = make_int2(src[i], __float_as_int(ea[i]));
    }
}

// ---------------- aggregation: one warp per node (fp32) ----------------
__global__ void k_agg(const float* __restrict__ h,
                      const float* __restrict__ lw, const float* __restrict__ lb,
                      const float* __restrict__ eps, int l,
                      float* __restrict__ out, int n) {
    int warp = (blockIdx.x * blockDim.x + threadIdx.x) >> 5;
    int lane = threadIdx.x & 31;
    if (warp >= n) return;
    int s0 = g_off[warp], s1 = g_off[warp + 1];
    float4 lw4 = *(const float4*)(lw + lane * 4);
    float4 lb4 = *(const float4*)(lb + lane * 4);
    float4 acc = make_float4(0.f, 0.f, 0.f, 0.f);
    #pragma unroll 4
    for (int e = s0; e < s1; ++e) {
        int2  p = g_edge[e];
        float a = __int_as_float(p.y);
        float4 hv = *(const float4*)(h + (size_t)p.x * D + lane * 4);
        acc.x += fmaxf(fmaf(a, lw4.x, lb4.x) + hv.x, 0.f);
        acc.y += fmaxf(fmaf(a, lw4.y, lb4.y) + hv.y, 0.f);
        acc.z += fmaxf(fmaf(a, lw4.z, lb4.z) + hv.z, 0.f);
        acc.w += fmaxf(fmaf(a, lw4.w, lb4.w) + hv.w, 0.f);
    }
    float inv = 1.f / (float)(s1 - s0);
    float g   = 1.f + eps[l];
    float4 hn = *(const float4*)(h + (size_t)warp * D + lane * 4);
    float4 o;
    o.x = acc.x * inv + g * hn.x;
    o.y = acc.y * inv + g * hn.y;
    o.z = acc.z * inv + g * hn.z;
    o.w = acc.w * inv + g * hn.w;
    *(float4*)(out + (size_t)warp * D + lane * 4) = o;
}

// ---------------- weight prep (also zeroes g_cnt): transpose + fp16 ------
__global__ void k_wprep(const float* __restrict__ w1, const float* __restrict__ w2,
                        const float* __restrict__ fw, int n) {
    int idx = blockIdx.x * blockDim.x + threadIdx.x;     // 40 * 128 * 32 = 163840
    if (idx < n) g_cnt[idx] = 0;
    if (idx >= 40 * 128 * 32) return;
    int ch  = idx >> 12;
    int rem = idx & 4095;
    int nn  = rem >> 5;
    int kk  = rem & 31;
    const float* W;
    int kg;
    if (ch < 24) {
        int g  = ch >> 2;
        int cw = ch & 3;
        int layer = g >> 1;
        W  = (g & 1) ? (w2 + (size_t)layer * D * D) : (w1 + (size_t)layer * D * D);
        kg = cw * 32 + kk;
    } else {
        int cw = ch - 24;
        W  = fw;
        kg = cw * 32 + kk;
    }
    g_wb[ch][nn * 40 + kk] = __float2half_rn(W[(size_t)kg * 128 + nn]);
}

// ---------------- HMMA / LDSM / cp.async helpers ----------------
__device__ __forceinline__ void mma_fp16(float* c, const uint32_t* a, uint32_t b0, uint32_t b1) {
    asm volatile(
        "mma.sync.aligned.m16n8k16.row.col.f32.f16.f16.f32 "
        "{%0,%1,%2,%3}, {%4,%5,%6,%7}, {%8,%9}, {%0,%1,%2,%3};"
        : "+f"(c[0]), "+f"(c[1]), "+f"(c[2]), "+f"(c[3])
        : "r"(a[0]), "r"(a[1]), "r"(a[2]), "r"(a[3]), "r"(b0), "r"(b1));
}

__device__ __forceinline__ void ldsm_x4(uint32_t* r, uint32_t addr) {
    asm volatile("ldmatrix.sync.aligned.m8n8.x4.shared.b16 {%0,%1,%2,%3}, [%4];"
                 : "=r"(r[0]), "=r"(r[1]), "=r"(r[2]), "=r"(r[3]) : "r"(addr));
}

__device__ __forceinline__ void cpasync16(uint32_t saddr, const void* gaddr) {
    asm volatile("cp.async.cg.shared.global [%0], [%1], 16;" :: "r"(saddr), "l"(gaddr));
}
__device__ __forceinline__ void cpasync_commit() { asm volatile("cp.async.commit_group;" ::: "memory"); }
__device__ __forceinline__ void cpasync_wait0()  { asm volatile("cp.async.wait_group 0;" ::: "memory"); }

__device__ __forceinline__ void split_fp16(float v, __half& hi, __half& lo) {
    hi = __float2half_rn(v);
    lo = __float2half_rn(v - __half2float(hi));
}

// stage one 10240B fp16 weight chunk (640 x 16B) via cp.async
__device__ __forceinline__ void stageB_async(uint32_t sbase, const __half* src, int tid) {
    #pragma unroll
    for (int i = 0; i < 3; ++i) {
        int t = tid + 256 * i;
        if (t < 640) cpasync16(sbase + t * 16, (const char*)src + t * 16);
    }
}

// pack 8 fp32 into hi/lo fp16 uint4s
__device__ __forceinline__ void pack8h(const float* v, uint4& hiq, uint4& loq) {
    uint32_t hw[4], lw_[4];
    #pragma unroll
    for (int q = 0; q < 4; ++q) {
        __half h0, l0, h1, l1;
        split_fp16(v[q * 2],     h0, l0);
        split_fp16(v[q * 2 + 1], h1, l1);
        __half2 hp = __halves2half2(h0, h1), lp = __halves2half2(l0, l1);
        hw[q]  = *(uint32_t*)&hp;
        lw_[q] = *(uint32_t*)&lp;
    }
    hiq = *(uint4*)hw;
    loq = *(uint4*)lw_;
}

#define SB_BUF_BYTES 10240     // 128 x 40 fp16
#define SA_LAYER_BYTES 9216    // 64 x 72 fp16
#define SMID_BYTES 33792       // 64 x 264 fp16
#define FA_BUF_BYTES 18432     // 128 x 72 fp16

// ---------------- fused layer MLP: h = relu(A@w1+b1)@w2+b2 ----------------
// 64x128 tile / 256 threads. KB=32 pipelined. fp16 2-pass: A = Ah+Al, B = fp16(W).
__global__ void __launch_bounds__(256) k_layer_mlp(
    const float* __restrict__ A, int wb1, int wb2,
    const float* __restrict__ bias1, const float* __restrict__ bias2,
    float* __restrict__ Cout, int M)
{
    extern __shared__ __align__(16) char dyn[];
    __half* sU = (__half*)dyn;                       // sMid / phase-1 sA double buf
    __half* sB = (__half*)(dyn + SMID_BYTES);        // 2 x weight chunk

    const int tid  = threadIdx.x;
    const int w    = tid >> 5;
    const int lane = tid & 31;
    const int wr   = w & 1;
    const int wc   = w >> 1;
    const int gid  = lane >> 2;
    const int tg   = lane & 3;
    const int lg   = lane >> 3;
    const int lr   = lane & 7;
    const int brow = blockIdx.x * 64;

    const uint32_t sUb = (uint32_t)__cvta_generic_to_shared(sU);
    const uint32_t sBb = (uint32_t)__cvta_generic_to_shared(sB);

    const int a_row_off = (lg & 1) * 8 + lr;
    const int a_k_off   = (lg >> 1) * 8;
    const int b_n_off   = (lg >> 1) * 8 + lr;
    const int b_k_off   = (lg & 1) * 8;

    float c[2][4][4];
    #pragma unroll
    for (int mt = 0; mt < 2; ++mt)
        #pragma unroll
        for (int nt = 0; nt < 4; ++nt)
            #pragma unroll
            for (int j = 0; j < 4; ++j) c[mt][nt][j] = 0.f;

    const int arow = tid >> 2;       // 0..63
    const int aq   = (tid & 3) * 8;  // 8 fp32 each
    const int grow = brow + arow;

    float v[8];
    // ---------- prologue: stage chunk 0 ----------
    stageB_async(sBb, g_wb[wb1], tid);
    cpasync_commit();
    if (grow < M) {
        float4 f0 = *(const float4*)(A + (size_t)grow * D + aq);
        float4 f1 = *(const float4*)(A + (size_t)grow * D + aq + 4);
        v[0]=f0.x; v[1]=f0.y; v[2]=f0.z; v[3]=f0.w; v[4]=f1.x; v[5]=f1.y; v[6]=f1.z; v[7]=f1.w;
    } else {
        #pragma unroll
        for (int i = 0; i < 8; ++i) v[i] = 0.f;
    }
    {
        uint4 hiq, loq; pack8h(v, hiq, loq);
        *(uint4*)&sU[arow * 72 + aq]      = hiq;
        *(uint4*)&sU[arow * 72 + 32 + aq] = loq;
    }
    cpasync_wait0();
    __syncthreads();

    // ================= phase 1: mid = A @ w1 (4 chunks, pipelined) ============
    int buf = 0;
    for (int ch = 0; ch < 4; ++ch) {
        const bool more = (ch < 3);
        stageB_async(sBb + (buf ^ 1) * SB_BUF_BYTES,
                     more ? g_wb[wb1 + ch + 1] : g_wb[wb2], tid);
        cpasync_commit();
        if (more && grow < M) {
            const float* ap = A + (size_t)grow * D + (ch + 1) * 32 + aq;
            float4 f0 = *(const float4*)(ap);
            float4 f1 = *(const float4*)(ap + 4);
            v[0]=f0.x; v[1]=f0.y; v[2]=f0.z; v[3]=f0.w; v[4]=f1.x; v[5]=f1.y; v[6]=f1.z; v[7]=f1.w;
        }
        const uint32_t aB = sUb + buf * SA_LAYER_BYTES;
        const uint32_t bB = sBb + buf * SB_BUF_BYTES;
        #pragma unroll
        for (int ks = 0; ks < 2; ++ks) {
            uint32_t b[2][4];
            #pragma unroll
            for (int np = 0; np < 2; ++np)
                ldsm_x4(b[np], bB + ((wc * 32 + np * 16 + b_n_off) * 40 + ks * 16 + b_k_off) * 2);
            #pragma unroll
            for (int p = 0; p < 2; ++p) {
                const int ak = p * 32 + ks * 16;
                uint32_t a[2][4];
                #pragma unroll
                for (int mt = 0; mt < 2; ++mt)
                    ldsm_x4(a[mt], aB + ((wr * 32 + mt * 16 + a_row_off) * 72 + ak + a_k_off) * 2);
                #pragma unroll
                for (int np = 0; np < 2; ++np) {
                    mma_fp16(c[0][np * 2],     a[0], b[np][0], b[np][1]);
                    mma_fp16(c[1][np * 2],     a[1], b[np][0], b[np][1]);
                    mma_fp16(c[0][np * 2 + 1], a[0], b[np][2], b[np][3]);
                    mma_fp16(c[1][np * 2 + 1], a[1], b[np][2], b[np][3]);
                }
            }
        }
        if (more) {
            uint4 hiq, loq; pack8h(v, hiq, loq);
            __half* sA1 = sU + (buf ^ 1) * (SA_LAYER_BYTES / 2);
            *(uint4*)&sA1[arow * 72 + aq]      = hiq;
            *(uint4*)&sA1[arow * 72 + 32 + aq] = loq;
        }
        cpasync_wait0();
        __syncthreads();
        buf ^= 1;
    }
    // buf now points at the staged w2 chunk 0.

    // ============ epilogue 1: bias + relu + fp16 split -> sMid ============
    float c2[2][4][4];
    #pragma unroll
    for (int mt = 0; mt < 2; ++mt) {
        #pragma unroll
        for (int nt = 0; nt < 4; ++nt) {
            int col = wc * 32 + nt * 8 + tg * 2;
            float bx = bias1[col], by = bias1[col + 1];
            #pragma unroll
            for (int half = 0; half < 2; ++half) {
                int r = wr * 32 + mt * 16 + gid + half * 8;
                float v0 = fmaxf(c[mt][nt][half * 2]     + bx, 0.f);
                float v1 = fmaxf(c[mt][nt][half * 2 + 1] + by, 0.f);
                __half h0, l0, h1, l1;
                split_fp16(v0, h0, l0);
                split_fp16(v1, h1, l1);
                __half2 hp = __halves2half2(h0, h1), lp = __halves2half2(l0, l1);
                *(uint32_t*)&sU[r * 264 + col]       = *(uint32_t*)&hp;
                *(uint32_t*)&sU[r * 264 + 128 + col] = *(uint32_t*)&lp;
            }
            #pragma unroll
            for (int j = 0; j < 4; ++j) c2[mt][nt][j] = 0.f;
        }
    }
    __syncthreads();

    // ================= phase 2: h = mid @ w2 (4 chunks; buf holds w2[0]) ============
    for (int ch = 0; ch < 4; ++ch) {
        if (ch < 3) {
            stageB_async(sBb + (buf ^ 1) * SB_BUF_BYTES, g_wb[wb2 + ch + 1], tid);
            cpasync_commit();
        }
        const uint32_t bB = sBb + buf * SB_BUF_BYTES;
        #pragma unroll
        for (int ks = 0; ks < 2; ++ks) {
            uint32_t b[2][4];
            #pragma unroll
            for (int np = 0; np < 2; ++np)
                ldsm_x4(b[np], bB + ((wc * 32 + np * 16 + b_n_off) * 40 + ks * 16 + b_k_off) * 2);
            #pragma unroll
            for (int p = 0; p < 2; ++p) {
                const int ak = ch * 32 + ks * 16 + p * 128;
                uint32_t a[2][4];
                #pragma unroll
                for (int mt = 0; mt < 2; ++mt)
                    ldsm_x4(a[mt], sUb + ((wr * 32 + mt * 16 + a_row_off) * 264 + ak + a_k_off) * 2);
                #pragma unroll
                for (int np = 0; np < 2; ++np) {
                    mma_fp16(c2[0][np * 2],     a[0], b[np][0], b[np][1]);
                    mma_fp16(c2[1][np * 2],     a[1], b[np][0], b[np][1]);
                    mma_fp16(c2[0][np * 2 + 1], a[0], b[np][2], b[np][3]);
                    mma_fp16(c2[1][np * 2 + 1], a[1], b[np][2], b[np][3]);
                }
            }
        }
        if (ch < 3) {
            cpasync_wait0();
            __syncthreads();
        }
        buf ^= 1;
    }

    // ============ epilogue 2: bias2 -> global ============
    #pragma unroll
    for (int mt = 0; mt < 2; ++mt) {
        #pragma unroll
        for (int nt = 0; nt < 4; ++nt) {
            int col = wc * 32 + nt * 8 + tg * 2;
            float bx = bias2[col], by = bias2[col + 1];
            int r0 = brow + wr * 32 + mt * 16 + gid;
            float v0 = c2[mt][nt][0] + bx, v1 = c2[mt][nt][1] + by;
            float v2 = c2[mt][nt][2] + bx, v3 = c2[mt][nt][3] + by;
            if (r0 < M)     *(float2*)(Cout + (size_t)r0 * D + col)       = make_float2(v0, v1);
            if (r0 + 8 < M) *(float2*)(Cout + (size_t)(r0 + 8) * D + col) = make_float2(v2, v3);
        }
    }
}

// ---------------- final GEMM: C = concat(A0..A3) @ W + bias (pipelined) ----
__global__ void __launch_bounds__(256) k_gemm_final(
    const float* __restrict__ A0, const float* __restrict__ A1,
    const float* __restrict__ A2, const float* __restrict__ A3,
    int wbase, const float* __restrict__ bias, float* __restrict__ C, int M)
{
    extern __shared__ __align__(16) char dyn[];
    __half* sA = (__half*)dyn;                        // 2 x 128*72
    __half* sB = (__half*)(dyn + 2 * FA_BUF_BYTES);   // 2 x 128*40

    const int tid  = threadIdx.x;
    const int w    = tid >> 5;
    const int lane = tid & 31;
    const int wr   = w & 3;
    const int wc   = w >> 2;
    const int gid  = lane >> 2;
    const int tg   = lane & 3;
    const int lg   = lane >> 3;
    const int lr   = lane & 7;
    const int brow = blockIdx.x * 128;

    const uint32_t sAb = (uint32_t)__cvta_generic_to_shared(sA);
    const uint32_t sBb = (uint32_t)__cvta_generic_to_shared(sB);

    const int a_row_off = (lg & 1) * 8 + lr;
    const int a_k_off   = (lg >> 1) * 8;
    const int b_n_off   = (lg >> 1) * 8 + lr;
    const int b_k_off   = (lg & 1) * 8;

    const float* srcs[4] = {A0, A1, A2, A3};

    float c[2][8][4];
    #pragma unroll
    for (int mt = 0; mt < 2; ++mt)
        #pragma unroll
        for (int nt = 0; nt < 8; ++nt)
            #pragma unroll
            for (int j = 0; j < 4; ++j) c[mt][nt][j] = 0.f;

    const int arow = tid >> 1;          // 0..127
    const int aq   = (tid & 1) * 16;    // 16 fp32 each
    const int grow = brow + arow;

    float v[16];
    auto loadA = [&](int ch) {
        if (grow < M) {
            const float* ap = srcs[ch >> 2] + (size_t)grow * D + (ch & 3) * 32 + aq;
            #pragma unroll
            for (int i = 0; i < 4; ++i) {
                float4 f = *(const float4*)(ap + i * 4);
                v[i * 4 + 0] = f.x; v[i * 4 + 1] = f.y; v[i * 4 + 2] = f.z; v[i * 4 + 3] = f.w;
            }
        } else {
            #pragma unroll
            for (int i = 0; i < 16; ++i) v[i] = 0.f;
        }
    };
    auto storeA = [&](int b) {
        __half* dst = sA + b * (FA_BUF_BYTES / 2);
        uint4 hiq, loq;
        pack8h(v, hiq, loq);
        *(uint4*)&dst[arow * 72 + aq]      = hiq;
        *(uint4*)&dst[arow * 72 + 32 + aq] = loq;
        pack8h(v + 8, hiq, loq);
        *(uint4*)&dst[arow * 72 + aq + 8]      = hiq;
        *(uint4*)&dst[arow * 72 + 32 + aq + 8] = loq;
    };

    // ---------- prologue ----------
    stageB_async(sBb, g_wb[wbase], tid);
    cpasync_commit();
    loadA(0);
    storeA(0);
    cpasync_wait0();
    __syncthreads();

    int buf = 0;
    for (int ch = 0; ch < 16; ++ch) {
        const bool more = (ch < 15);
        if (more) {
            stageB_async(sBb + (buf ^ 1) * SB_BUF_BYTES, g_wb[wbase + ch + 1], tid);
            cpasync_commit();
            loadA(ch + 1);
        }
        const uint32_t aB = sAb + buf * FA_BUF_BYTES;
        const uint32_t bB = sBb + buf * SB_BUF_BYTES;
        #pragma unroll
        for (int ks = 0; ks < 2; ++ks) {
            uint32_t b[4][4];
            #pragma unroll
            for (int np = 0; np < 4; ++np)
                ldsm_x4(b[np], bB + ((wc * 64 + np * 16 + b_n_off) * 40 + ks * 16 + b_k_off) * 2);
            #pragma unroll
            for (int p = 0; p < 2; ++p) {
                const int ak = p * 32 + ks * 16;
                uint32_t a[2][4];
                #pragma unroll
                for (int mt = 0; mt < 2; ++mt)
                    ldsm_x4(a[mt], aB + ((wr * 32 + mt * 16 + a_row_off) * 72 + ak + a_k_off) * 2);
                #pragma unroll
                for (int np = 0; np < 4; ++np) {
                    mma_fp16(c[0][np * 2],     a[0], b[np][0], b[np][1]);
                    mma_fp16(c[1][np * 2],     a[1], b[np][0], b[np][1]);
                    mma_fp16(c[0][np * 2 + 1], a[0], b[np][2], b[np][3]);
                    mma_fp16(c[1][np * 2 + 1], a[1], b[np][2], b[np][3]);
                }
            }
        }
        if (more) storeA(buf ^ 1);
        cpasync_wait0();
        __syncthreads();
        buf ^= 1;
    }

    #pragma unroll
    for (int mt = 0; mt < 2; ++mt) {
        #pragma unroll
        for (int nt = 0; nt < 8; ++nt) {
            int col  = wc * 64 + nt * 8 + tg * 2;
            float bx = bias[col], by = bias[col + 1];
            int r0 = brow + wr * 32 + mt * 16 + gid;
            float v0 = c[mt][nt][0] + bx, v1 = c[mt][nt][1] + by;
            float v2 = c[mt][nt][2] + bx, v3 = c[mt][nt][3] + by;
            if (r0 < M)     *(float2*)(C + (size_t)r0 * D + col)       = make_float2(v0, v1);
            if (r0 + 8 < M) *(float2*)(C + (size_t)(r0 + 8) * D + col) = make_float2(v2, v3);
        }
    }
}

// ---------------- launcher ----------------
extern "C" void kernel_launch(void* const* d_in, const int* in_sizes, int n_in,
                              void* d_out, int out_size) {
    const float* x   = (const float*)d_in[0];
    const int*   ei  = (const int*)  d_in[1];
    const float* ea  = (const float*)d_in[2];
    const float* lw  = (const float*)d_in[3];
    const float* lb  = (const float*)d_in[4];
    const float* eps = (const float*)d_in[5];
    const float* w1  = (const float*)d_in[6];
    const float* b1  = (const float*)d_in[7];
    const float* w2  = (const float*)d_in[8];
    const float* b2  = (const float*)d_in[9];
    const float* fw  = (const float*)d_in[10];
    const float* fb  = (const float*)d_in[11];
    float* out = (float*)d_out;

    const int N = in_sizes[0] / D;
    const int E = in_sizes[2];

    const int MLP_SMEM   = SMID_BYTES + 2 * SB_BUF_BYTES;       // 54272
    const int FINAL_SMEM = 2 * FA_BUF_BYTES + 2 * SB_BUF_BYTES; // 57344
    cudaFuncSetAttribute(k_layer_mlp,  cudaFuncAttributeMaxDynamicSharedMemorySize, MLP_SMEM);
    cudaFuncSetAttribute(k_gemm_final, cudaFuncAttributeMaxDynamicSharedMemorySize, FINAL_SMEM);

    float *hbuf, *tmp;
    cudaGetSymbolAddress((void**)&hbuf, g_h);
    cudaGetSymbolAddress((void**)&tmp,  g_tmp);

    // weight prep (also zeroes g_cnt) + CSR build
    k_wprep<<<(40 * 128 * 32 + 255) / 256, 256>>>(w1, w2, fw, N);
    k_hist<<<(E + 255) / 256, 256>>>(ei + E, E);
    const int nb = (N + 1023) / 1024;
    k_scan1<<<nb, 1024>>>(N);
    k_scan3<<<nb, 1024>>>(N);
    k_scatter<<<(E + 255) / 256, 256>>>(ei, ei + E, ea, E);

    const float* h = x;
    for (int l = 0; l < 3; ++l) {
        float* hl = hbuf + (size_t)l * NMAX * D;
        k_agg<<<(N + 7) / 8, 256>>>(h, lw + l * D, lb + l * D, eps, l, tmp, N);
        k_layer_mlp<<<(N + 63) / 64, 256, MLP_SMEM>>>(tmp, (l * 2 + 0) * 4, (l * 2 + 1) * 4,
                                                      b1 + l * D, b2 + l * D, hl, N);
        h = hl;
    }

    // final: [x | h1 | h2 | h3] @ fw + fb
    k_gemm_final<<<(N + 127) / 128, 256, FINAL_SMEM>>>(x, hbuf, hbuf + (size_t)NMAX * D,
                                                       hbuf + (size_t)2 * NMAX * D, 24, fb, out, N);
}

// round 15
// speedup vs baseline: 1.2787x; 1.0534x over previous
#include <cuda_runtime.h>
#include <cuda_fp16.h>
#include <cstdint>

#define NMAX 50000
#define EMAX 800000
#define D 128

// ---------------- device scratch (no allocations allowed) ----------------
__device__ int      g_cnt[NMAX];
__device__ int      g_off[NMAX + 1];
__device__ int      g_cur[NMAX];
__device__ int2     g_edge[EMAX];       // {src, attr-bits}
__device__ int      g_bsum[64];
__device__ unsigned g_barctr = 0;       // monotonic grid-barrier counter (scan)
__device__ float    g_h[3][NMAX * D];   // h1, h2, h3
// agg output, fp16 split: row = [hi 0..127 | lo 0..127]
__device__ __align__(16) __half g_tmp[NMAX * 256];
// prepacked fp16 weight chunks: 40 chunks (6 layer-GEMMs x 4 + final x 16), KB=32.
__device__ __align__(16) __half g_wb[40][128 * 40];

// ---------------- preprocessing: CSR by target via counting sort ----------------
__global__ void k_hist(const int* __restrict__ tgt, int E) {
    int i = blockIdx.x * blockDim.x + threadIdx.x;
    if (i < E) atomicAdd(&g_cnt[tgt[i]], 1);
}

__device__ __forceinline__ int block_scan_incl(int v) {
    __shared__ int wsum[32];
    const int lane = threadIdx.x & 31;
    const int wid  = threadIdx.x >> 5;
    int s = v;
    #pragma unroll
    for (int d = 1; d < 32; d <<= 1) {
        int t = __shfl_up_sync(0xFFFFFFFFu, s, d);
        if (lane >= d) s += t;
    }
    if (lane == 31) wsum[wid] = s;
    __syncthreads();
    if (wid == 0) {
        int ws = wsum[lane];
        #pragma unroll
        for (int d = 1; d < 32; d <<= 1) {
            int t = __shfl_up_sync(0xFFFFFFFFu, ws, d);
            if (lane >= d) ws += t;
        }
        wsum[lane] = ws;
    }
    __syncthreads();
    return s + (wid ? wsum[wid - 1] : 0);
}

// monotonic grid barrier: safe across graph replays; all nb blocks resident (nb<=49)
__device__ __forceinline__ void grid_bar(int nb) {
    __syncthreads();
    if (threadIdx.x == 0) {
        __threadfence();
        unsigned arrival = atomicAdd(&g_barctr, 1) + 1;
        unsigned target  = ((arrival + nb - 1) / nb) * nb;
        while (atomicAdd(&g_barctr, 0u) < target) {}
        __threadfence();
    }
    __syncthreads();
}

// fused scan: block-local inclusive scan + grid barrier + block-prefix fixup
__global__ void __launch_bounds__(1024) k_scan(int n, int nb) {
    int i = blockIdx.x * 1024 + threadIdx.x;
    int v = (i < n) ? g_cnt[i] : 0;
    int incl = block_scan_incl(v);
    if (i < n) g_off[i + 1] = incl;
    if (threadIdx.x == 1023) g_bsum[blockIdx.x] = incl;

    grid_bar(nb);

    __shared__ int pre;
    if (threadIdx.x < 32) {
        int s = 0;
        for (int j = threadIdx.x; j < (int)blockIdx.x; j += 32) s += g_bsum[j];
        #pragma unroll
        for (int d = 16; d; d >>= 1) s += __shfl_down_sync(0xFFFFFFFFu, s, d);
        if (threadIdx.x == 0) pre = s;
    }
    __syncthreads();
    if (i < n) {
        int off = g_off[i + 1] + pre;
        g_off[i + 1] = off;
        g_cur[i]     = off - g_cnt[i];
    }
    if (i == 0) g_off[0] = 0;
}

__global__ void k_scatter(const int* __restrict__ src, const int* __restrict__ tgt,
                          const float* __restrict__ ea, int E) {
    int i = blockIdx.x * blockDim.x + threadIdx.x;
    if (i < E) {
        int p = atomicAdd(&g_cur[tgt[i]], 1);
        g_edge[p] = make_int2(src[i], __float_as_int(ea[i]));
    }
}

// ---------------- fp16 split helpers ----------------
__device__ __forceinline__ void split_fp16(float v, __half& hi, __half& lo) {
    hi = __float2half_rn(v);
    lo = __float2half_rn(v - __half2float(hi));
}

// ---------------- aggregation: one warp per node, 4-edge batched ----------------
// writes fp16 hi|lo split directly into g_tmp row [hi0..127 | lo0..127]
__global__ void k_agg(const float* __restrict__ h,
                      const float* __restrict__ lw, const float* __restrict__ lb,
                      const float* __restrict__ eps, int l,
                      __half* __restrict__ out, int n) {
    int warp = (blockIdx.x * blockDim.x + threadIdx.x) >> 5;
    int lane = threadIdx.x & 31;
    if (warp >= n) return;
    int s0 = g_off[warp], s1 = g_off[warp + 1];
    float4 lw4 = *(const float4*)(lw + lane * 4);
    float4 lb4 = *(const float4*)(lb + lane * 4);
    float4 acc = make_float4(0.f, 0.f, 0.f, 0.f);

    int e = s0;
    for (; e + 4 <= s1; e += 4) {
        int2 p0 = g_edge[e + 0];
        int2 p1 = g_edge[e + 1];
        int2 p2 = g_edge[e + 2];
        int2 p3 = g_edge[e + 3];
        float4 h0 = *(const float4*)(h + (size_t)p0.x * D + lane * 4);
        float4 h1 = *(const float4*)(h + (size_t)p1.x * D + lane * 4);
        float4 h2 = *(const float4*)(h + (size_t)p2.x * D + lane * 4);
        float4 h3 = *(const float4*)(h + (size_t)p3.x * D + lane * 4);
        float a0 = __int_as_float(p0.y), a1 = __int_as_float(p1.y);
        float a2 = __int_as_float(p2.y), a3 = __int_as_float(p3.y);
        acc.x += fmaxf(fmaf(a0, lw4.x, lb4.x) + h0.x, 0.f);
        acc.y += fmaxf(fmaf(a0, lw4.y, lb4.y) + h0.y, 0.f);
        acc.z += fmaxf(fmaf(a0, lw4.z, lb4.z) + h0.z, 0.f);
        acc.w += fmaxf(fmaf(a0, lw4.w, lb4.w) + h0.w, 0.f);
        acc.x += fmaxf(fmaf(a1, lw4.x, lb4.x) + h1.x, 0.f);
        acc.y += fmaxf(fmaf(a1, lw4.y, lb4.y) + h1.y, 0.f);
        acc.z += fmaxf(fmaf(a1, lw4.z, lb4.z) + h1.z, 0.f);
        acc.w += fmaxf(fmaf(a1, lw4.w, lb4.w) + h1.w, 0.f);
        acc.x += fmaxf(fmaf(a2, lw4.x, lb4.x) + h2.x, 0.f);
        acc.y += fmaxf(fmaf(a2, lw4.y, lb4.y) + h2.y, 0.f);
        acc.z += fmaxf(fmaf(a2, lw4.z, lb4.z) + h2.z, 0.f);
        acc.w += fmaxf(fmaf(a2, lw4.w, lb4.w) + h2.w, 0.f);
        acc.x += fmaxf(fmaf(a3, lw4.x, lb4.x) + h3.x, 0.f);
        acc.y += fmaxf(fmaf(a3, lw4.y, lb4.y) + h3.y, 0.f);
        acc.z += fmaxf(fmaf(a3, lw4.z, lb4.z) + h3.z, 0.f);
        acc.w += fmaxf(fmaf(a3, lw4.w, lb4.w) + h3.w, 0.f);
    }
    for (; e < s1; ++e) {
        int2  p = g_edge[e];
        float a = __int_as_float(p.y);
        float4 hv = *(const float4*)(h + (size_t)p.x * D + lane * 4);
        acc.x += fmaxf(fmaf(a, lw4.x, lb4.x) + hv.x, 0.f);
        acc.y += fmaxf(fmaf(a, lw4.y, lb4.y) + hv.y, 0.f);
        acc.z += fmaxf(fmaf(a, lw4.z, lb4.z) + hv.z, 0.f);
        acc.w += fmaxf(fmaf(a, lw4.w, lb4.w) + hv.w, 0.f);
    }

    float inv = 1.f / (float)(s1 - s0);
    float g   = 1.f + eps[l];
    float4 hn = *(const float4*)(h + (size_t)warp * D + lane * 4);
    float o0 = acc.x * inv + g * hn.x;
    float o1 = acc.y * inv + g * hn.y;
    float o2 = acc.z * inv + g * hn.z;
    float o3 = acc.w * inv + g * hn.w;

    __half h0, l0, h1, l1, h2, l2, h3, l3;
    split_fp16(o0, h0, l0);
    split_fp16(o1, h1, l1);
    split_fp16(o2, h2, l2);
    split_fp16(o3, h3, l3);
    __half2 hpA = __halves2half2(h0, h1), hpB = __halves2half2(h2, h3);
    __half2 lpA = __halves2half2(l0, l1), lpB = __halves2half2(l2, l3);
    uint2 hiq = make_uint2(*(uint32_t*)&hpA, *(uint32_t*)&hpB);
    uint2 loq = make_uint2(*(uint32_t*)&lpA, *(uint32_t*)&lpB);
    *(uint2*)(out + (size_t)warp * 256 + lane * 4)       = hiq;
    *(uint2*)(out + (size_t)warp * 256 + 128 + lane * 4) = loq;
}

// ---------------- weight prep (also zeroes g_cnt): transpose + fp16 ------
__global__ void k_wprep(const float* __restrict__ w1, const float* __restrict__ w2,
                        const float* __restrict__ fw, int n) {
    int idx = blockIdx.x * blockDim.x + threadIdx.x;     // 40 * 128 * 32 = 163840
    if (idx < n) g_cnt[idx] = 0;
    if (idx >= 40 * 128 * 32) return;
    int ch  = idx >> 12;
    int rem = idx & 4095;
    int nn  = rem >> 5;
    int kk  = rem & 31;
    const float* W;
    int kg;
    if (ch < 24) {
        int g  = ch >> 2;
        int cw = ch & 3;
        int layer = g >> 1;
        W  = (g & 1) ? (w2 + (size_t)layer * D * D) : (w1 + (size_t)layer * D * D);
        kg = cw * 32 + kk;
    } else {
        int cw = ch - 24;
        W  = fw;
        kg = cw * 32 + kk;
    }
    g_wb[ch][nn * 40 + kk] = __float2half_rn(W[(size_t)kg * 128 + nn]);
}

// ---------------- HMMA / LDSM / cp.async helpers ----------------
__device__ __forceinline__ void mma_fp16(float* c, const uint32_t* a, uint32_t b0, uint32_t b1) {
    asm volatile(
        "mma.sync.aligned.m16n8k16.row.col.f32.f16.f16.f32 "
        "{%0,%1,%2,%3}, {%4,%5,%6,%7}, {%8,%9}, {%0,%1,%2,%3};"
        : "+f"(c[0]), "+f"(c[1]), "+f"(c[2]), "+f"(c[3])
        : "r"(a[0]), "r"(a[1]), "r"(a[2]), "r"(a[3]), "r"(b0), "r"(b1));
}

__device__ __forceinline__ void ldsm_x4(uint32_t* r, uint32_t addr) {
    asm volatile("ldmatrix.sync.aligned.m8n8.x4.shared.b16 {%0,%1,%2,%3}, [%4];"
                 : "=r"(r[0]), "=r"(r[1]), "=r"(r[2]), "=r"(r[3]) : "r"(addr));
}

__device__ __forceinline__ void cpasync16(uint32_t saddr, const void* gaddr) {
    asm volatile("cp.async.cg.shared.global [%0], [%1], 16;" :: "r"(saddr), "l"(gaddr));
}
__device__ __forceinline__ void cpasync_commit() { asm volatile("cp.async.commit_group;" ::: "memory"); }
__device__ __forceinline__ void cpasync_wait0()  { asm volatile("cp.async.wait_group 0;" ::: "memory"); }

// stage one 10240B fp16 weight chunk (640 x 16B) via cp.async
__device__ __forceinline__ void stageB_async(uint32_t sbase, const __half* src, int tid) {
    #pragma unroll
    for (int i = 0; i < 3; ++i) {
        int t = tid + 256 * i;
        if (t < 640) cpasync16(sbase + t * 16, (const char*)src + t * 16);
    }
}

// pack 8 fp32 into hi/lo fp16 uint4s (final GEMM A staging)
__device__ __forceinline__ void pack8h(const float* v, uint4& hiq, uint4& loq) {
    uint32_t hw[4], lw_[4];
    #pragma unroll
    for (int q = 0; q < 4; ++q) {
        __half h0, l0, h1, l1;
        split_fp16(v[q * 2],     h0, l0);
        split_fp16(v[q * 2 + 1], h1, l1);
        __half2 hp = __halves2half2(h0, h1), lp = __halves2half2(l0, l1);
        hw[q]  = *(uint32_t*)&hp;
        lw_[q] = *(uint32_t*)&lp;
    }
    hiq = *(uint4*)hw;
    loq = *(uint4*)lw_;
}

#define SB_BUF_BYTES 10240     // 128 x 40 fp16
#define SA_LAYER_BYTES 9216    // 64 x 72 fp16
#define SMID_BYTES 33792       // 64 x 264 fp16
#define FA_BUF_BYTES 18432     // 128 x 72 fp16

// ---------------- fused layer MLP: h = relu(A@w1+b1)@w2+b2 ----------------
// A is the fp16 hi|lo split produced by k_agg -> staging is a straight copy.
__global__ void __launch_bounds__(256) k_layer_mlp(
    const __half* __restrict__ A, int wb1, int wb2,
    const float* __restrict__ bias1, const float* __restrict__ bias2,
    float* __restrict__ Cout, int M)
{
    extern __shared__ __align__(16) char dyn[];
    __half* sU = (__half*)dyn;                       // sMid / phase-1 sA double buf
    __half* sB = (__half*)(dyn + SMID_BYTES);        // 2 x weight chunk

    const int tid  = threadIdx.x;
    const int w    = tid >> 5;
    const int lane = tid & 31;
    const int wr   = w & 1;
    const int wc   = w >> 1;
    const int gid  = lane >> 2;
    const int tg   = lane & 3;
    const int lg   = lane >> 3;
    const int lr   = lane & 7;
    const int brow = blockIdx.x * 64;

    const uint32_t sUb = (uint32_t)__cvta_generic_to_shared(sU);
    const uint32_t sBb = (uint32_t)__cvta_generic_to_shared(sB);

    const int a_row_off = (lg & 1) * 8 + lr;
    const int a_k_off   = (lg >> 1) * 8;
    const int b_n_off   = (lg >> 1) * 8 + lr;
    const int b_k_off   = (lg & 1) * 8;

    float c[2][4][4];
    #pragma unroll
    for (int mt = 0; mt < 2; ++mt)
        #pragma unroll
        for (int nt = 0; nt < 4; ++nt)
            #pragma unroll
            for (int j = 0; j < 4; ++j) c[mt][nt][j] = 0.f;

    const int arow = tid >> 2;       // 0..63
    const int aq   = (tid & 3) * 8;  // 8 fp16 per load
    const int grow = brow + arow;

    uint4 vhi, vlo;
    auto loadAchunk = [&](int ch) {
        if (grow < M) {
            const __half* ap = A + (size_t)grow * 256 + ch * 32 + aq;
            vhi = *(const uint4*)(ap);
            vlo = *(const uint4*)(ap + 128);
        } else {
            vhi = make_uint4(0, 0, 0, 0);
            vlo = make_uint4(0, 0, 0, 0);
        }
    };

    // ---------- prologue: stage chunk 0 ----------
    stageB_async(sBb, g_wb[wb1], tid);
    cpasync_commit();
    loadAchunk(0);
    *(uint4*)&sU[arow * 72 + aq]      = vhi;
    *(uint4*)&sU[arow * 72 + 32 + aq] = vlo;
    cpasync_wait0();
    __syncthreads();

    // ================= phase 1: mid = A @ w1 (4 chunks, pipelined) ============
    int buf = 0;
    for (int ch = 0; ch < 4; ++ch) {
        const bool more = (ch < 3);
        stageB_async(sBb + (buf ^ 1) * SB_BUF_BYTES,
                     more ? g_wb[wb1 + ch + 1] : g_wb[wb2], tid);
        cpasync_commit();
        if (more) loadAchunk(ch + 1);
        const uint32_t aB = sUb + buf * SA_LAYER_BYTES;
        const uint32_t bB = sBb + buf * SB_BUF_BYTES;
        #pragma unroll
        for (int ks = 0; ks < 2; ++ks) {
            uint32_t b[2][4];
            #pragma unroll
            for (int np = 0; np < 2; ++np)
                ldsm_x4(b[np], bB + ((wc * 32 + np * 16 + b_n_off) * 40 + ks * 16 + b_k_off) * 2);
            #pragma unroll
            for (int p = 0; p < 2; ++p) {
                const int ak = p * 32 + ks * 16;
                uint32_t a[2][4];
                #pragma unroll
                for (int mt = 0; mt < 2; ++mt)
                    ldsm_x4(a[mt], aB + ((wr * 32 + mt * 16 + a_row_off) * 72 + ak + a_k_off) * 2);
                #pragma unroll
                for (int np = 0; np < 2; ++np) {
                    mma_fp16(c[0][np * 2],     a[0], b[np][0], b[np][1]);
                    mma_fp16(c[1][np * 2],     a[1], b[np][0], b[np][1]);
                    mma_fp16(c[0][np * 2 + 1], a[0], b[np][2], b[np][3]);
                    mma_fp16(c[1][np * 2 + 1], a[1], b[np][2], b[np][3]);
                }
            }
        }
        if (more) {
            __half* sA1 = sU + (buf ^ 1) * (SA_LAYER_BYTES / 2);
            *(uint4*)&sA1[arow * 72 + aq]      = vhi;
            *(uint4*)&sA1[arow * 72 + 32 + aq] = vlo;
        }
        cpasync_wait0();
        __syncthreads();
        buf ^= 1;
    }
    // buf now points at the staged w2 chunk 0.

    // ============ epilogue 1: bias + relu + fp16 split -> sMid ============
    float c2[2][4][4];
    #pragma unroll
    for (int mt = 0; mt < 2; ++mt) {
        #pragma unroll
        for (int nt = 0; nt < 4; ++nt) {
            int col = wc * 32 + nt * 8 + tg * 2;
            float bx = bias1[col], by = bias1[col + 1];
            #pragma unroll
            for (int half = 0; half < 2; ++half) {
                int r = wr * 32 + mt * 16 + gid + half * 8;
                float v0 = fmaxf(c[mt][nt][half * 2]     + bx, 0.f);
                float v1 = fmaxf(c[mt][nt][half * 2 + 1] + by, 0.f);
                __half h0, l0, h1, l1;
                split_fp16(v0, h0, l0);
                split_fp16(v1, h1, l1);
                __half2 hp = __halves2half2(h0, h1), lp = __halves2half2(l0, l1);
                *(uint32_t*)&sU[r * 264 + col]       = *(uint32_t*)&hp;
                *(uint32_t*)&sU[r * 264 + 128 + col] = *(uint32_t*)&lp;
            }
            #pragma unroll
            for (int j = 0; j < 4; ++j) c2[mt][nt][j] = 0.f;
        }
    }
    __syncthreads();

    // ================= phase 2: h = mid @ w2 (4 chunks; buf holds w2[0]) ============
    for (int ch = 0; ch < 4; ++ch) {
        if (ch < 3) {
            stageB_async(sBb + (buf ^ 1) * SB_BUF_BYTES, g_wb[wb2 + ch + 1], tid);
            cpasync_commit();
        }
        const uint32_t bB = sBb + buf * SB_BUF_BYTES;
        #pragma unroll
        for (int ks = 0; ks < 2; ++ks) {
            uint32_t b[2][4];
            #pragma unroll
            for (int np = 0; np < 2; ++np)
                ldsm_x4(b[np], bB + ((wc * 32 + np * 16 + b_n_off) * 40 + ks * 16 + b_k_off) * 2);
            #pragma unroll
            for (int p = 0; p < 2; ++p) {
                const int ak = ch * 32 + ks * 16 + p * 128;
                uint32_t a[2][4];
                #pragma unroll
                for (int mt = 0; mt < 2; ++mt)
                    ldsm_x4(a[mt], sUb + ((wr * 32 + mt * 16 + a_row_off) * 264 + ak + a_k_off) * 2);
                #pragma unroll
                for (int np = 0; np < 2; ++np) {
                    mma_fp16(c2[0][np * 2],     a[0], b[np][0], b[np][1]);
                    mma_fp16(c2[1][np * 2],     a[1], b[np][0], b[np][1]);
                    mma_fp16(c2[0][np * 2 + 1], a[0], b[np][2], b[np][3]);
                    mma_fp16(c2[1][np * 2 + 1], a[1], b[np][2], b[np][3]);
                }
            }
        }
        if (ch < 3) {
            cpasync_wait0();
            __syncthreads();
        }
        buf ^= 1;
    }

    // ============ epilogue 2: bias2 -> global ============
    #pragma unroll
    for (int mt = 0; mt < 2; ++mt) {
        #pragma unroll
        for (int nt = 0; nt < 4; ++nt) {
            int col = wc * 32 + nt * 8 + tg * 2;
            float bx = bias2[col], by = bias2[col + 1];
            int r0 = brow + wr * 32 + mt * 16 + gid;
            float v0 = c2[mt][nt][0] + bx, v1 = c2[mt][nt][1] + by;
            float v2 = c2[mt][nt][2] + bx, v3 = c2[mt][nt][3] + by;
            if (r0 < M)     *(float2*)(Cout + (size_t)r0 * D + col)       = make_float2(v0, v1);
            if (r0 + 8 < M) *(float2*)(Cout + (size_t)(r0 + 8) * D + col) = make_float2(v2, v3);
        }
    }
}

// ---------------- final GEMM: C = concat(A0..A3) @ W + bias (pipelined) ----
__global__ void __launch_bounds__(256) k_gemm_final(
    const float* __restrict__ A0, const float* __restrict__ A1,
    const float* __restrict__ A2, const float* __restrict__ A3,
    int wbase, const float* __restrict__ bias, float* __restrict__ C, int M)
{
    extern __shared__ __align__(16) char dyn[];
    __half* sA = (__half*)dyn;                        // 2 x 128*72
    __half* sB = (__half*)(dyn + 2 * FA_BUF_BYTES);   // 2 x 128*40

    const int tid  = threadIdx.x;
    const int w    = tid >> 5;
    const int lane = tid & 31;
    const int wr   = w & 3;
    const int wc   = w >> 2;
    const int gid  = lane >> 2;
    const int tg   = lane & 3;
    const int lg   = lane >> 3;
    const int lr   = lane & 7;
    const int brow = blockIdx.x * 128;

    const uint32_t sAb = (uint32_t)__cvta_generic_to_shared(sA);
    const uint32_t sBb = (uint32_t)__cvta_generic_to_shared(sB);

    const int a_row_off = (lg & 1) * 8 + lr;
    const int a_k_off   = (lg >> 1) * 8;
    const int b_n_off   = (lg >> 1) * 8 + lr;
    const int b_k_off   = (lg & 1) * 8;

    const float* srcs[4] = {A0, A1, A2, A3};

    float c[2][8][4];
    #pragma unroll
    for (int mt = 0; mt < 2; ++mt)
        #pragma unroll
        for (int nt = 0; nt < 8; ++nt)
            #pragma unroll
            for (int j = 0; j < 4; ++j) c[mt][nt][j] = 0.f;

    const int arow = tid >> 1;          // 0..127
    const int aq   = (tid & 1) * 16;    // 16 fp32 each
    const int grow = brow + arow;

    float v[16];
    auto loadA = [&](int ch) {
        if (grow < M) {
            const float* ap = srcs[ch >> 2] + (size_t)grow * D + (ch & 3) * 32 + aq;
            #pragma unroll
            for (int i = 0; i < 4; ++i) {
                float4 f = *(const float4*)(ap + i * 4);
                v[i * 4 + 0] = f.x; v[i * 4 + 1] = f.y; v[i * 4 + 2] = f.z; v[i * 4 + 3] = f.w;
            }
        } else {
            #pragma unroll
            for (int i = 0; i < 16; ++i) v[i] = 0.f;
        }
    };
    auto storeA = [&](int b) {
        __half* dst = sA + b * (FA_BUF_BYTES / 2);
        uint4 hiq, loq;
        pack8h(v, hiq, loq);
        *(uint4*)&dst[arow * 72 + aq]      = hiq;
        *(uint4*)&dst[arow * 72 + 32 + aq] = loq;
        pack8h(v + 8, hiq, loq);
        *(uint4*)&dst[arow * 72 + aq + 8]      = hiq;
        *(uint4*)&dst[arow * 72 + 32 + aq + 8] = loq;
    };

    // ---------- prologue ----------
    stageB_async(sBb, g_wb[wbase], tid);
    cpasync_commit();
    loadA(0);
    storeA(0);
    cpasync_wait0();
    __syncthreads();

    int buf = 0;
    for (int ch = 0; ch < 16; ++ch) {
        const bool more = (ch < 15);
        if (more) {
            stageB_async(sBb + (buf ^ 1) * SB_BUF_BYTES, g_wb[wbase + ch + 1], tid);
            cpasync_commit();
            loadA(ch + 1);
        }
        const uint32_t aB = sAb + buf * FA_BUF_BYTES;
        const uint32_t bB = sBb + buf * SB_BUF_BYTES;
        #pragma unroll
        for (int ks = 0; ks < 2; ++ks) {
            uint32_t b[4][4];
            #pragma unroll
            for (int np = 0; np < 4; ++np)
                ldsm_x4(b[np], bB + ((wc * 64 + np * 16 + b_n_off) * 40 + ks * 16 + b_k_off) * 2);
            #pragma unroll
            for (int p = 0; p < 2; ++p) {
                const int ak = p * 32 + ks * 16;
                uint32_t a[2][4];
                #pragma unroll
                for (int mt = 0; mt < 2; ++mt)
                    ldsm_x4(a[mt], aB + ((wr * 32 + mt * 16 + a_row_off) * 72 + ak + a_k_off) * 2);
                #pragma unroll
                for (int np = 0; np < 4; ++np) {
                    mma_fp16(c[0][np * 2],     a[0], b[np][0], b[np][1]);
                    mma_fp16(c[1][np * 2],     a[1], b[np][0], b[np][1]);
                    mma_fp16(c[0][np * 2 + 1], a[0], b[np][2], b[np][3]);
                    mma_fp16(c[1][np * 2 + 1], a[1], b[np][2], b[np][3]);
                }
            }
        }
        if (more) storeA(buf ^ 1);
        cpasync_wait0();
        __syncthreads();
        buf ^= 1;
    }

    #pragma unroll
    for (int mt = 0; mt < 2; ++mt) {
        #pragma unroll
        for (int nt = 0; nt < 8; ++nt) {
            int col  = wc * 64 + nt * 8 + tg * 2;
            float bx = bias[col], by = bias[col + 1];
            int r0 = brow + wr * 32 + mt * 16 + gid;
            float v0 = c[mt][nt][0] + bx, v1 = c[mt][nt][1] + by;
            float v2 = c[mt][nt][2] + bx, v3 = c[mt][nt][3] + by;
            if (r0 < M)     *(float2*)(C + (size_t)r0 * D + col)       = make_float2(v0, v1);
            if (r0 + 8 < M) *(float2*)(C + (size_t)(r0 + 8) * D + col) = make_float2(v2, v3);
        }
    }
}

// ---------------- launcher ----------------
extern "C" void kernel_launch(void* const* d_in, const int* in_sizes, int n_in,
                              void* d_out, int out_size) {
    const float* x   = (const float*)d_in[0];
    const int*   ei  = (const int*)  d_in[1];
    const float* ea  = (const float*)d_in[2];
    const float* lw  = (const float*)d_in[3];
    const float* lb  = (const float*)d_in[4];
    const float* eps = (const float*)d_in[5];
    const float* w1  = (const float*)d_in[6];
    const float* b1  = (const float*)d_in[7];
    const float* w2  = (const float*)d_in[8];
    const float* b2  = (const float*)d_in[9];
    const float* fw  = (const float*)d_in[10];
    const float* fb  = (const float*)d_in[11];
    float* out = (float*)d_out;

    const int N = in_sizes[0] / D;
    const int E = in_sizes[2];

    const int MLP_SMEM   = SMID_BYTES + 2 * SB_BUF_BYTES;       // 54272
    const int FINAL_SMEM = 2 * FA_BUF_BYTES + 2 * SB_BUF_BYTES; // 57344
    cudaFuncSetAttribute(k_layer_mlp,  cudaFuncAttributeMaxDynamicSharedMemorySize, MLP_SMEM);
    cudaFuncSetAttribute(k_gemm_final, cudaFuncAttributeMaxDynamicSharedMemorySize, FINAL_SMEM);

    float* hbuf;
    __half* tmp;
    cudaGetSymbolAddress((void**)&hbuf, g_h);
    cudaGetSymbolAddress((void**)&tmp,  g_tmp);

    // weight prep (also zeroes g_cnt) + CSR build (fused scan)
    k_wprep<<<(40 * 128 * 32 + 255) / 256, 256>>>(w1, w2, fw, N);
    k_hist<<<(E + 255) / 256, 256>>>(ei + E, E);
    const int nb = (N + 1023) / 1024;
    k_scan<<<nb, 1024>>>(N, nb);
    k_scatter<<<(E + 255) / 256, 256>>>(ei, ei + E, ea, E);

    const float* h = x;
    for (int l = 0; l < 3; ++l) {
        float* hl = hbuf + (size_t)l * NMAX * D;
        k_agg<<<(N + 7) / 8, 256>>>(h, lw + l * D, lb + l * D, eps, l, tmp, N);
        k_layer_mlp<<<(N + 63) / 64, 256, MLP_SMEM>>>(tmp, (l * 2 + 0) * 4, (l * 2 + 1) * 4,
                                                      b1 + l * D, b2 + l * D, hl, N);
        h = hl;
    }

    // final: [x | h1 | h2 | h3] @ fw + fb
    k_gemm_final<<<(N + 127) / 128, 256, FINAL_SMEM>>>(x, hbuf, hbuf + (size_t)NMAX * D,
                                                       hbuf + (size_t)2 * NMAX * D, 24, fb, out, N);
}

// round 16
// speedup vs baseline: 1.2922x; 1.0105x over previous
#include <cuda_runtime.h>
#include <cuda_fp16.h>
#include <cstdint>

#define NMAX 50000
#define EMAX 800000
#define D 128

// ---------------- device scratch (no allocations allowed) ----------------
__device__ int      g_cnt[NMAX];
__device__ int      g_off[NMAX + 1];
__device__ int      g_cur[NMAX];
__device__ int2     g_edge[EMAX];       // {src, attr-bits}
__device__ int      g_bsum[64];
__device__ unsigned g_barctr = 0;       // monotonic grid-barrier counter (scan)
__device__ float    g_h[3][NMAX * D];   // h1, h2, h3
// agg output, fp16 split: row = [hi 0..127 | lo 0..127]
__device__ __align__(16) __half g_tmp[NMAX * 256];
// prepacked fp16 weight chunks: 40 chunks (6 layer-GEMMs x 4 + final x 16), KB=32.
__device__ __align__(16) __half g_wb[40][128 * 40];

// ---------------- preprocessing: CSR by target via counting sort ----------------
// 2 edges per thread for ILP (latency-bound atomics)
__global__ void k_hist(const int* __restrict__ tgt, int E) {
    int i = (blockIdx.x * blockDim.x + threadIdx.x) * 2;
    if (i + 1 < E) {
        int t0 = tgt[i], t1 = tgt[i + 1];
        atomicAdd(&g_cnt[t0], 1);
        atomicAdd(&g_cnt[t1], 1);
    } else if (i < E) {
        atomicAdd(&g_cnt[tgt[i]], 1);
    }
}

__device__ __forceinline__ int block_scan_incl(int v) {
    __shared__ int wsum[32];
    const int lane = threadIdx.x & 31;
    const int wid  = threadIdx.x >> 5;
    int s = v;
    #pragma unroll
    for (int d = 1; d < 32; d <<= 1) {
        int t = __shfl_up_sync(0xFFFFFFFFu, s, d);
        if (lane >= d) s += t;
    }
    if (lane == 31) wsum[wid] = s;
    __syncthreads();
    if (wid == 0) {
        int ws = wsum[lane];
        #pragma unroll
        for (int d = 1; d < 32; d <<= 1) {
            int t = __shfl_up_sync(0xFFFFFFFFu, ws, d);
            if (lane >= d) ws += t;
        }
        wsum[lane] = ws;
    }
    __syncthreads();
    return s + (wid ? wsum[wid - 1] : 0);
}

// monotonic grid barrier: safe across graph replays; all nb blocks resident (nb<=49)
__device__ __forceinline__ void grid_bar(int nb) {
    __syncthreads();
    if (threadIdx.x == 0) {
        __threadfence();
        unsigned arrival = atomicAdd(&g_barctr, 1) + 1;
        unsigned target  = ((arrival + nb - 1) / nb) * nb;
        while (atomicAdd(&g_barctr, 0u) < target) {}
        __threadfence();
    }
    __syncthreads();
}

// fused scan: block-local inclusive scan + grid barrier + block-prefix fixup
__global__ void __launch_bounds__(1024) k_scan(int n, int nb) {
    int i = blockIdx.x * 1024 + threadIdx.x;
    int v = (i < n) ? g_cnt[i] : 0;
    int incl = block_scan_incl(v);
    if (i < n) g_off[i + 1] = incl;
    if (threadIdx.x == 1023) g_bsum[blockIdx.x] = incl;

    grid_bar(nb);

    __shared__ int pre;
    if (threadIdx.x < 32) {
        int s = 0;
        for (int j = threadIdx.x; j < (int)blockIdx.x; j += 32) s += g_bsum[j];
        #pragma unroll
        for (int d = 16; d; d >>= 1) s += __shfl_down_sync(0xFFFFFFFFu, s, d);
        if (threadIdx.x == 0) pre = s;
    }
    __syncthreads();
    if (i < n) {
        int off = g_off[i + 1] + pre;
        g_off[i + 1] = off;
        g_cur[i]     = off - g_cnt[i];
    }
    if (i == 0) g_off[0] = 0;
}

// 2 edges per thread for ILP
__global__ void k_scatter(const int* __restrict__ src, const int* __restrict__ tgt,
                          const float* __restrict__ ea, int E) {
    int i = (blockIdx.x * blockDim.x + threadIdx.x) * 2;
    if (i + 1 < E) {
        int t0 = tgt[i], t1 = tgt[i + 1];
        int s0 = src[i], s1 = src[i + 1];
        float a0 = ea[i], a1 = ea[i + 1];
        int p0 = atomicAdd(&g_cur[t0], 1);
        int p1 = atomicAdd(&g_cur[t1], 1);
        g_edge[p0] = make_int2(s0, __float_as_int(a0));
        g_edge[p1] = make_int2(s1, __float_as_int(a1));
    } else if (i < E) {
        int p = atomicAdd(&g_cur[tgt[i]], 1);
        g_edge[p] = make_int2(src[i], __float_as_int(ea[i]));
    }
}

// ---------------- fp16 split helpers ----------------
__device__ __forceinline__ void split_fp16(float v, __half& hi, __half& lo) {
    hi = __float2half_rn(v);
    lo = __float2half_rn(v - __half2float(hi));
}

// ---------------- aggregation: one warp per node, 8-edge batched ----------------
// writes fp16 hi|lo split directly into g_tmp row [hi0..127 | lo0..127]
__global__ void k_agg(const float* __restrict__ h,
                      const float* __restrict__ lw, const float* __restrict__ lb,
                      const float* __restrict__ eps, int l,
                      __half* __restrict__ out, int n) {
    int warp = (blockIdx.x * blockDim.x + threadIdx.x) >> 5;
    int lane = threadIdx.x & 31;
    if (warp >= n) return;
    int s0 = g_off[warp], s1 = g_off[warp + 1];
    float4 lw4 = *(const float4*)(lw + lane * 4);
    float4 lb4 = *(const float4*)(lb + lane * 4);
    float4 acc = make_float4(0.f, 0.f, 0.f, 0.f);

    int e = s0;
    for (; e + 8 <= s1; e += 8) {
        int2 p[8];
        #pragma unroll
        for (int j = 0; j < 8; ++j) p[j] = g_edge[e + j];
        float4 hv[8];
        #pragma unroll
        for (int j = 0; j < 8; ++j)
            hv[j] = *(const float4*)(h + (size_t)p[j].x * D + lane * 4);
        #pragma unroll
        for (int j = 0; j < 8; ++j) {
            float a = __int_as_float(p[j].y);
            acc.x += fmaxf(fmaf(a, lw4.x, lb4.x) + hv[j].x, 0.f);
            acc.y += fmaxf(fmaf(a, lw4.y, lb4.y) + hv[j].y, 0.f);
            acc.z += fmaxf(fmaf(a, lw4.z, lb4.z) + hv[j].z, 0.f);
            acc.w += fmaxf(fmaf(a, lw4.w, lb4.w) + hv[j].w, 0.f);
        }
    }
    for (; e + 4 <= s1; e += 4) {
        int2 p[4];
        #pragma unroll
        for (int j = 0; j < 4; ++j) p[j] = g_edge[e + j];
        float4 hv[4];
        #pragma unroll
        for (int j = 0; j < 4; ++j)
            hv[j] = *(const float4*)(h + (size_t)p[j].x * D + lane * 4);
        #pragma unroll
        for (int j = 0; j < 4; ++j) {
            float a = __int_as_float(p[j].y);
            acc.x += fmaxf(fmaf(a, lw4.x, lb4.x) + hv[j].x, 0.f);
            acc.y += fmaxf(fmaf(a, lw4.y, lb4.y) + hv[j].y, 0.f);
            acc.z += fmaxf(fmaf(a, lw4.z, lb4.z) + hv[j].z, 0.f);
            acc.w += fmaxf(fmaf(a, lw4.w, lb4.w) + hv[j].w, 0.f);
        }
    }
    for (; e < s1; ++e) {
        int2  p = g_edge[e];
        float a = __int_as_float(p.y);
        float4 hv = *(const float4*)(h + (size_t)p.x * D + lane * 4);
        acc.x += fmaxf(fmaf(a, lw4.x, lb4.x) + hv.x, 0.f);
        acc.y += fmaxf(fmaf(a, lw4.y, lb4.y) + hv.y, 0.f);
        acc.z += fmaxf(fmaf(a, lw4.z, lb4.z) + hv.z, 0.f);
        acc.w += fmaxf(fmaf(a, lw4.w, lb4.w) + hv.w, 0.f);
    }

    float inv = 1.f / (float)(s1 - s0);
    float g   = 1.f + eps[l];
    float4 hn = *(const float4*)(h + (size_t)warp * D + lane * 4);
    float o0 = acc.x * inv + g * hn.x;
    float o1 = acc.y * inv + g * hn.y;
    float o2 = acc.z * inv + g * hn.z;
    float o3 = acc.w * inv + g * hn.w;

    __half h0, l0, h1, l1, h2, l2, h3, l3;
    split_fp16(o0, h0, l0);
    split_fp16(o1, h1, l1);
    split_fp16(o2, h2, l2);
    split_fp16(o3, h3, l3);
    __half2 hpA = __halves2half2(h0, h1), hpB = __halves2half2(h2, h3);
    __half2 lpA = __halves2half2(l0, l1), lpB = __halves2half2(l2, l3);
    uint2 hiq = make_uint2(*(uint32_t*)&hpA, *(uint32_t*)&hpB);
    uint2 loq = make_uint2(*(uint32_t*)&lpA, *(uint32_t*)&lpB);
    *(uint2*)(out + (size_t)warp * 256 + lane * 4)       = hiq;
    *(uint2*)(out + (size_t)warp * 256 + 128 + lane * 4) = loq;
}

// ---------------- weight prep (also zeroes g_cnt): transpose + fp16 ------
__global__ void k_wprep(const float* __restrict__ w1, const float* __restrict__ w2,
                        const float* __restrict__ fw, int n) {
    int idx = blockIdx.x * blockDim.x + threadIdx.x;     // 40 * 128 * 32 = 163840
    if (idx < n) g_cnt[idx] = 0;
    if (idx >= 40 * 128 * 32) return;
    int ch  = idx >> 12;
    int rem = idx & 4095;
    int nn  = rem >> 5;
    int kk  = rem & 31;
    const float* W;
    int kg;
    if (ch < 24) {
        int g  = ch >> 2;
        int cw = ch & 3;
        int layer = g >> 1;
        W  = (g & 1) ? (w2 + (size_t)layer * D * D) : (w1 + (size_t)layer * D * D);
        kg = cw * 32 + kk;
    } else {
        int cw = ch - 24;
        W  = fw;
        kg = cw * 32 + kk;
    }
    g_wb[ch][nn * 40 + kk] = __float2half_rn(W[(size_t)kg * 128 + nn]);
}

// ---------------- HMMA / LDSM / cp.async helpers ----------------
__device__ __forceinline__ void mma_fp16(float* c, const uint32_t* a, uint32_t b0, uint32_t b1) {
    asm volatile(
        "mma.sync.aligned.m16n8k16.row.col.f32.f16.f16.f32 "
        "{%0,%1,%2,%3}, {%4,%5,%6,%7}, {%8,%9}, {%0,%1,%2,%3};"
        : "+f"(c[0]), "+f"(c[1]), "+f"(c[2]), "+f"(c[3])
        : "r"(a[0]), "r"(a[1]), "r"(a[2]), "r"(a[3]), "r"(b0), "r"(b1));
}

__device__ __forceinline__ void ldsm_x4(uint32_t* r, uint32_t addr) {
    asm volatile("ldmatrix.sync.aligned.m8n8.x4.shared.b16 {%0,%1,%2,%3}, [%4];"
                 : "=r"(r[0]), "=r"(r[1]), "=r"(r[2]), "=r"(r[3]) : "r"(addr));
}

__device__ __forceinline__ void cpasync16(uint32_t saddr, const void* gaddr) {
    asm volatile("cp.async.cg.shared.global [%0], [%1], 16;" :: "r"(saddr), "l"(gaddr));
}
__device__ __forceinline__ void cpasync_commit() { asm volatile("cp.async.commit_group;" ::: "memory"); }
__device__ __forceinline__ void cpasync_wait0()  { asm volatile("cp.async.wait_group 0;" ::: "memory"); }

// stage one 10240B fp16 weight chunk (640 x 16B) via cp.async
__device__ __forceinline__ void stageB_async(uint32_t sbase, const __half* src, int tid) {
    #pragma unroll
    for (int i = 0; i < 3; ++i) {
        int t = tid + 256 * i;
        if (t < 640) cpasync16(sbase + t * 16, (const char*)src + t * 16);
    }
}

// pack 8 fp32 into hi/lo fp16 uint4s (final GEMM A staging)
__device__ __forceinline__ void pack8h(const float* v, uint4& hiq, uint4& loq) {
    uint32_t hw[4], lw_[4];
    #pragma unroll
    for (int q = 0; q < 4; ++q) {
        __half h0, l0, h1, l1;
        split_fp16(v[q * 2],     h0, l0);
        split_fp16(v[q * 2 + 1], h1, l1);
        __half2 hp = __halves2half2(h0, h1), lp = __halves2half2(l0, l1);
        hw[q]  = *(uint32_t*)&hp;
        lw_[q] = *(uint32_t*)&lp;
    }
    hiq = *(uint4*)hw;
    loq = *(uint4*)lw_;
}

#define SB_BUF_BYTES 10240     // 128 x 40 fp16
#define SA_LAYER_BYTES 9216    // 64 x 72 fp16
#define SMID_BYTES 33792       // 64 x 264 fp16
#define FA_BUF_BYTES 18432     // 128 x 72 fp16

// ---------------- fused layer MLP: h = relu(A@w1+b1)@w2+b2 ----------------
// A is the fp16 hi|lo split produced by k_agg -> staging is a straight copy.
__global__ void __launch_bounds__(256) k_layer_mlp(
    const __half* __restrict__ A, int wb1, int wb2,
    const float* __restrict__ bias1, const float* __restrict__ bias2,
    float* __restrict__ Cout, int M)
{
    extern __shared__ __align__(16) char dyn[];
    __half* sU = (__half*)dyn;                       // sMid / phase-1 sA double buf
    __half* sB = (__half*)(dyn + SMID_BYTES);        // 2 x weight chunk

    const int tid  = threadIdx.x;
    const int w    = tid >> 5;
    const int lane = tid & 31;
    const int wr   = w & 1;
    const int wc   = w >> 1;
    const int gid  = lane >> 2;
    const int tg   = lane & 3;
    const int lg   = lane >> 3;
    const int lr   = lane & 7;
    const int brow = blockIdx.x * 64;

    const uint32_t sUb = (uint32_t)__cvta_generic_to_shared(sU);
    const uint32_t sBb = (uint32_t)__cvta_generic_to_shared(sB);

    const int a_row_off = (lg & 1) * 8 + lr;
    const int a_k_off   = (lg >> 1) * 8;
    const int b_n_off   = (lg >> 1) * 8 + lr;
    const int b_k_off   = (lg & 1) * 8;

    float c[2][4][4];
    #pragma unroll
    for (int mt = 0; mt < 2; ++mt)
        #pragma unroll
        for (int nt = 0; nt < 4; ++nt)
            #pragma unroll
            for (int j = 0; j < 4; ++j) c[mt][nt][j] = 0.f;

    const int arow = tid >> 2;       // 0..63
    const int aq   = (tid & 3) * 8;  // 8 fp16 per load
    const int grow = brow + arow;

    uint4 vhi, vlo;
    auto loadAchunk = [&](int ch) {
        if (grow < M) {
            const __half* ap = A + (size_t)grow * 256 + ch * 32 + aq;
            vhi = *(const uint4*)(ap);
            vlo = *(const uint4*)(ap + 128);
        } else {
            vhi = make_uint4(0, 0, 0, 0);
            vlo = make_uint4(0, 0, 0, 0);
        }
    };

    // ---------- prologue: stage chunk 0 ----------
    stageB_async(sBb, g_wb[wb1], tid);
    cpasync_commit();
    loadAchunk(0);
    *(uint4*)&sU[arow * 72 + aq]      = vhi;
    *(uint4*)&sU[arow * 72 + 32 + aq] = vlo;
    cpasync_wait0();
    __syncthreads();

    // ================= phase 1: mid = A @ w1 (4 chunks, pipelined) ============
    int buf = 0;
    for (int ch = 0; ch < 4; ++ch) {
        const bool more = (ch < 3);
        stageB_async(sBb + (buf ^ 1) * SB_BUF_BYTES,
                     more ? g_wb[wb1 + ch + 1] : g_wb[wb2], tid);
        cpasync_commit();
        if (more) loadAchunk(ch + 1);
        const uint32_t aB = sUb + buf * SA_LAYER_BYTES;
        const uint32_t bB = sBb + buf * SB_BUF_BYTES;
        #pragma unroll
        for (int ks = 0; ks < 2; ++ks) {
            uint32_t b[2][4];
            #pragma unroll
            for (int np = 0; np < 2; ++np)
                ldsm_x4(b[np], bB + ((wc * 32 + np * 16 + b_n_off) * 40 + ks * 16 + b_k_off) * 2);
            #pragma unroll
            for (int p = 0; p < 2; ++p) {
                const int ak = p * 32 + ks * 16;
                uint32_t a[2][4];
                #pragma unroll
                for (int mt = 0; mt < 2; ++mt)
                    ldsm_x4(a[mt], aB + ((wr * 32 + mt * 16 + a_row_off) * 72 + ak + a_k_off) * 2);
                #pragma unroll
                for (int np = 0; np < 2; ++np) {
                    mma_fp16(c[0][np * 2],     a[0], b[np][0], b[np][1]);
                    mma_fp16(c[1][np * 2],     a[1], b[np][0], b[np][1]);
                    mma_fp16(c[0][np * 2 + 1], a[0], b[np][2], b[np][3]);
                    mma_fp16(c[1][np * 2 + 1], a[1], b[np][2], b[np][3]);
                }
            }
        }
        if (more) {
            __half* sA1 = sU + (buf ^ 1) * (SA_LAYER_BYTES / 2);
            *(uint4*)&sA1[arow * 72 + aq]      = vhi;
            *(uint4*)&sA1[arow * 72 + 32 + aq] = vlo;
        }
        cpasync_wait0();
        __syncthreads();
        buf ^= 1;
    }
    // buf now points at the staged w2 chunk 0.

    // ============ epilogue 1: bias + relu + fp16 split -> sMid ============
    float c2[2][4][4];
    #pragma unroll
    for (int mt = 0; mt < 2; ++mt) {
        #pragma unroll
        for (int nt = 0; nt < 4; ++nt) {
            int col = wc * 32 + nt * 8 + tg * 2;
            float bx = bias1[col], by = bias1[col + 1];
            #pragma unroll
            for (int half = 0; half < 2; ++half) {
                int r = wr * 32 + mt * 16 + gid + half * 8;
                float v0 = fmaxf(c[mt][nt][half * 2]     + bx, 0.f);
                float v1 = fmaxf(c[mt][nt][half * 2 + 1] + by, 0.f);
                __half h0, l0, h1, l1;
                split_fp16(v0, h0, l0);
                split_fp16(v1, h1, l1);
                __half2 hp = __halves2half2(h0, h1), lp = __halves2half2(l0, l1);
                *(uint32_t*)&sU[r * 264 + col]       = *(uint32_t*)&hp;
                *(uint32_t*)&sU[r * 264 + 128 + col] = *(uint32_t*)&lp;
            }
            #pragma unroll
            for (int j = 0; j < 4; ++j) c2[mt][nt][j] = 0.f;
        }
    }
    __syncthreads();

    // ================= phase 2: h = mid @ w2 (4 chunks; buf holds w2[0]) ============
    for (int ch = 0; ch < 4; ++ch) {
        if (ch < 3) {
            stageB_async(sBb + (buf ^ 1) * SB_BUF_BYTES, g_wb[wb2 + ch + 1], tid);
            cpasync_commit();
        }
        const uint32_t bB = sBb + buf * SB_BUF_BYTES;
        #pragma unroll
        for (int ks = 0; ks < 2; ++ks) {
            uint32_t b[2][4];
            #pragma unroll
            for (int np = 0; np < 2; ++np)
                ldsm_x4(b[np], bB + ((wc * 32 + np * 16 + b_n_off) * 40 + ks * 16 + b_k_off) * 2);
            #pragma unroll
            for (int p = 0; p < 2; ++p) {
                const int ak = ch * 32 + ks * 16 + p * 128;
                uint32_t a[2][4];
                #pragma unroll
                for (int mt = 0; mt < 2; ++mt)
                    ldsm_x4(a[mt], sUb + ((wr * 32 + mt * 16 + a_row_off) * 264 + ak + a_k_off) * 2);
                #pragma unroll
                for (int np = 0; np < 2; ++np) {
                    mma_fp16(c2[0][np * 2],     a[0], b[np][0], b[np][1]);
                    mma_fp16(c2[1][np * 2],     a[1], b[np][0], b[np][1]);
                    mma_fp16(c2[0][np * 2 + 1], a[0], b[np][2], b[np][3]);
                    mma_fp16(c2[1][np * 2 + 1], a[1], b[np][2], b[np][3]);
                }
            }
        }
        if (ch < 3) {
            cpasync_wait0();
            __syncthreads();
        }
        buf ^= 1;
    }

    // ============ epilogue 2: bias2 -> global ============
    #pragma unroll
    for (int mt = 0; mt < 2; ++mt) {
        #pragma unroll
        for (int nt = 0; nt < 4; ++nt) {
            int col = wc * 32 + nt * 8 + tg * 2;
            float bx = bias2[col], by = bias2[col + 1];
            int r0 = brow + wr * 32 + mt * 16 + gid;
            float v0 = c2[mt][nt][0] + bx, v1 = c2[mt][nt][1] + by;
            float v2 = c2[mt][nt][2] + bx, v3 = c2[mt][nt][3] + by;
            if (r0 < M)     *(float2*)(Cout + (size_t)r0 * D + col)       = make_float2(v0, v1);
            if (r0 + 8 < M) *(float2*)(Cout + (size_t)(r0 + 8) * D + col) = make_float2(v2, v3);
        }
    }
}

// ---------------- final GEMM: C = concat(A0..A3) @ W + bias (pipelined) ----
__global__ void __launch_bounds__(256) k_gemm_final(
    const float* __restrict__ A0, const float* __restrict__ A1,
    const float* __restrict__ A2, const float* __restrict__ A3,
    int wbase, const float* __restrict__ bias, float* __restrict__ C, int M)
{
    extern __shared__ __align__(16) char dyn[];
    __half* sA = (__half*)dyn;                        // 2 x 128*72
    __half* sB = (__half*)(dyn + 2 * FA_BUF_BYTES);   // 2 x 128*40

    const int tid  = threadIdx.x;
    const int w    = tid >> 5;
    const int lane = tid & 31;
    const int wr   = w & 3;
    const int wc   = w >> 2;
    const int gid  = lane >> 2;
    const int tg   = lane & 3;
    const int lg   = lane >> 3;
    const int lr   = lane & 7;
    const int brow = blockIdx.x * 128;

    const uint32_t sAb = (uint32_t)__cvta_generic_to_shared(sA);
    const uint32_t sBb = (uint32_t)__cvta_generic_to_shared(sB);

    const int a_row_off = (lg & 1) * 8 + lr;
    const int a_k_off   = (lg >> 1) * 8;
    const int b_n_off   = (lg >> 1) * 8 + lr;
    const int b_k_off   = (lg & 1) * 8;

    const float* srcs[4] = {A0, A1, A2, A3};

    float c[2][8][4];
    #pragma unroll
    for (int mt = 0; mt < 2; ++mt)
        #pragma unroll
        for (int nt = 0; nt < 8; ++nt)
            #pragma unroll
            for (int j = 0; j < 4; ++j) c[mt][nt][j] = 0.f;

    const int arow = tid >> 1;          // 0..127
    const int aq   = (tid & 1) * 16;    // 16 fp32 each
    const int grow = brow + arow;

    float v[16];
    auto loadA = [&](int ch) {
        if (grow < M) {
            const float* ap = srcs[ch >> 2] + (size_t)grow * D + (ch & 3) * 32 + aq;
            #pragma unroll
            for (int i = 0; i < 4; ++i) {
                float4 f = *(const float4*)(ap + i * 4);
                v[i * 4 + 0] = f.x; v[i * 4 + 1] = f.y; v[i * 4 + 2] = f.z; v[i * 4 + 3] = f.w;
            }
        } else {
            #pragma unroll
            for (int i = 0; i < 16; ++i) v[i] = 0.f;
        }
    };
    auto storeA = [&](int b) {
        __half* dst = sA + b * (FA_BUF_BYTES / 2);
        uint4 hiq, loq;
        pack8h(v, hiq, loq);
        *(uint4*)&dst[arow * 72 + aq]      = hiq;
        *(uint4*)&dst[arow * 72 + 32 + aq] = loq;
        pack8h(v + 8, hiq, loq);
        *(uint4*)&dst[arow * 72 + aq + 8]      = hiq;
        *(uint4*)&dst[arow * 72 + 32 + aq + 8] = loq;
    };

    // ---------- prologue ----------
    stageB_async(sBb, g_wb[wbase], tid);
    cpasync_commit();
    loadA(0);
    storeA(0);
    cpasync_wait0();
    __syncthreads();

    int buf = 0;
    for (int ch = 0; ch < 16; ++ch) {
        const bool more = (ch < 15);
        if (more) {
            stageB_async(sBb + (buf ^ 1) * SB_BUF_BYTES, g_wb[wbase + ch + 1], tid);
            cpasync_commit();
            loadA(ch + 1);
        }
        const uint32_t aB = sAb + buf * FA_BUF_BYTES;
        const uint32_t bB = sBb + buf * SB_BUF_BYTES;
        #pragma unroll
        for (int ks = 0; ks < 2; ++ks) {
            uint32_t b[4][4];
            #pragma unroll
            for (int np = 0; np < 4; ++np)
                ldsm_x4(b[np], bB + ((wc * 64 + np * 16 + b_n_off) * 40 + ks * 16 + b_k_off) * 2);
            #pragma unroll
            for (int p = 0; p < 2; ++p) {
                const int ak = p * 32 + ks * 16;
                uint32_t a[2][4];
                #pragma unroll
                for (int mt = 0; mt < 2; ++mt)
                    ldsm_x4(a[mt], aB + ((wr * 32 + mt * 16 + a_row_off) * 72 + ak + a_k_off) * 2);
                #pragma unroll
                for (int np = 0; np < 4; ++np) {
                    mma_fp16(c[0][np * 2],     a[0], b[np][0], b[np][1]);
                    mma_fp16(c[1][np * 2],     a[1], b[np][0], b[np][1]);
                    mma_fp16(c[0][np * 2 + 1], a[0], b[np][2], b[np][3]);
                    mma_fp16(c[1][np * 2 + 1], a[1], b[np][2], b[np][3]);
                }
            }
        }
        if (more) storeA(buf ^ 1);
        cpasync_wait0();
        __syncthreads();
        buf ^= 1;
    }

    #pragma unroll
    for (int mt = 0; mt < 2; ++mt) {
        #pragma unroll
        for (int nt = 0; nt < 8; ++nt) {
            int col  = wc * 64 + nt * 8 + tg * 2;
            float bx = bias[col], by = bias[col + 1];
            int r0 = brow + wr * 32 + mt * 16 + gid;
            float v0 = c[mt][nt][0] + bx, v1 = c[mt][nt][1] + by;
            float v2 = c[mt][nt][2] + bx, v3 = c[mt][nt][3] + by;
            if (r0 < M)     *(float2*)(C + (size_t)r0 * D + col)       = make_float2(v0, v1);
            if (r0 + 8 < M) *(float2*)(C + (size_t)(r0 + 8) * D + col) = make_float2(v2, v3);
        }
    }
}

// ---------------- launcher ----------------
extern "C" void kernel_launch(void* const* d_in, const int* in_sizes, int n_in,
                              void* d_out, int out_size) {
    const float* x   = (const float*)d_in[0];
    const int*   ei  = (const int*)  d_in[1];
    const float* ea  = (const float*)d_in[2];
    const float* lw  = (const float*)d_in[3];
    const float* lb  = (const float*)d_in[4];
    const float* eps = (const float*)d_in[5];
    const float* w1  = (const float*)d_in[6];
    const float* b1  = (const float*)d_in[7];
    const float* w2  = (const float*)d_in[8];
    const float* b2  = (const float*)d_in[9];
    const float* fw  = (const float*)d_in[10];
    const float* fb  = (const float*)d_in[11];
    float* out = (float*)d_out;

    const int N = in_sizes[0] / D;
    const int E = in_sizes[2];

    const int MLP_SMEM   = SMID_BYTES + 2 * SB_BUF_BYTES;       // 54272
    const int FINAL_SMEM = 2 * FA_BUF_BYTES + 2 * SB_BUF_BYTES; // 57344
    cudaFuncSetAttribute(k_layer_mlp,  cudaFuncAttributeMaxDynamicSharedMemorySize, MLP_SMEM);
    cudaFuncSetAttribute(k_gemm_final, cudaFuncAttributeMaxDynamicSharedMemorySize, FINAL_SMEM);

    float* hbuf;
    __half* tmp;
    cudaGetSymbolAddress((void**)&hbuf, g_h);
    cudaGetSymbolAddress((void**)&tmp,  g_tmp);

    // weight prep (also zeroes g_cnt) + CSR build (fused scan)
    k_wprep<<<(40 * 128 * 32 + 255) / 256, 256>>>(w1, w2, fw, N);
    k_hist<<<(E / 2 + 256) / 256, 256>>>(ei + E, E);
    const int nb = (N + 1023) / 1024;
    k_scan<<<nb, 1024>>>(N, nb);
    k_scatter<<<(E / 2 + 256) / 256, 256>>>(ei, ei + E, ea, E);

    const float* h = x;
    for (int l = 0; l < 3; ++l) {
        float* hl = hbuf + (size_t)l * NMAX * D;
        k_agg<<<(N + 7) / 8, 256>>>(h, lw + l * D, lb + l * D, eps, l, tmp, N);
        k_layer_mlp<<<(N + 63) / 64, 256, MLP_SMEM>>>(tmp, (l * 2 + 0) * 4, (l * 2 + 1) * 4,
                                                      b1 + l * D, b2 + l * D, hl, N);
        h = hl;
    }

    // final: [x | h1 | h2 | h3] @ fw + fb
    k_gemm_final<<<(N + 127) / 128, 256, FINAL_SMEM>>>(x, hbuf, hbuf + (size_t)NMAX * D,
                                                       hbuf + (size_t)2 * NMAX * D, 24, fb, out, N);
}

// round 17
// speedup vs baseline: 1.3336x; 1.0321x over previous
#include <cuda_runtime.h>
#include <cuda_fp16.h>
#include <cstdint>

#define NMAX 50000
#define EMAX 800000
#define D 128

// ---------------- device scratch (no allocations allowed) ----------------
__device__ int      g_cnt[NMAX];
__device__ int      g_off[NMAX + 1];
__device__ int      g_cur[NMAX];
__device__ int2     g_edge[EMAX];       // {src, attr-bits}
__device__ int      g_bsum[64];
__device__ unsigned g_barctr = 0;       // monotonic grid-barrier counter (scan)
__device__ float    g_h[3][NMAX * D];   // h1, h2, h3
// agg output, plain fp16 (A-lo dropped for phase-1 GEMM)
__device__ __align__(16) __half g_tmp[NMAX * 128];
// prepacked fp16 weight chunks: 40 chunks (6 layer-GEMMs x 4 + final x 16), KB=32.
__device__ __align__(16) __half g_wb[40][128 * 40];

// ---------------- preprocessing: CSR by target via counting sort ----------------
__global__ void k_hist(const int* __restrict__ tgt, int E) {
    int i = blockIdx.x * blockDim.x + threadIdx.x;
    if (i < E) atomicAdd(&g_cnt[tgt[i]], 1);
}

__device__ __forceinline__ int block_scan_incl(int v) {
    __shared__ int wsum[32];
    const int lane = threadIdx.x & 31;
    const int wid  = threadIdx.x >> 5;
    int s = v;
    #pragma unroll
    for (int d = 1; d < 32; d <<= 1) {
        int t = __shfl_up_sync(0xFFFFFFFFu, s, d);
        if (lane >= d) s += t;
    }
    if (lane == 31) wsum[wid] = s;
    __syncthreads();
    if (wid == 0) {
        int ws = wsum[lane];
        #pragma unroll
        for (int d = 1; d < 32; d <<= 1) {
            int t = __shfl_up_sync(0xFFFFFFFFu, ws, d);
            if (lane >= d) ws += t;
        }
        wsum[lane] = ws;
    }
    __syncthreads();
    return s + (wid ? wsum[wid - 1] : 0);
}

// monotonic grid barrier: safe across graph replays; all nb blocks resident (nb<=49)
__device__ __forceinline__ void grid_bar(int nb) {
    __syncthreads();
    if (threadIdx.x == 0) {
        __threadfence();
        unsigned arrival = atomicAdd(&g_barctr, 1) + 1;
        unsigned target  = ((arrival + nb - 1) / nb) * nb;
        while (atomicAdd(&g_barctr, 0u) < target) {}
        __threadfence();
    }
    __syncthreads();
}

// fused scan: block-local inclusive scan + grid barrier + block-prefix fixup
__global__ void __launch_bounds__(1024) k_scan(int n, int nb) {
    int i = blockIdx.x * 1024 + threadIdx.x;
    int v = (i < n) ? g_cnt[i] : 0;
    int incl = block_scan_incl(v);
    if (i < n) g_off[i + 1] = incl;
    if (threadIdx.x == 1023) g_bsum[blockIdx.x] = incl;

    grid_bar(nb);

    __shared__ int pre;
    if (threadIdx.x < 32) {
        int s = 0;
        for (int j = threadIdx.x; j < (int)blockIdx.x; j += 32) s += g_bsum[j];
        #pragma unroll
        for (int d = 16; d; d >>= 1) s += __shfl_down_sync(0xFFFFFFFFu, s, d);
        if (threadIdx.x == 0) pre = s;
    }
    __syncthreads();
    if (i < n) {
        int off = g_off[i + 1] + pre;
        g_off[i + 1] = off;
        g_cur[i]     = off - g_cnt[i];
    }
    if (i == 0) g_off[0] = 0;
}

__global__ void k_scatter(const int* __restrict__ src, const int* __restrict__ tgt,
                          const float* __restrict__ ea, int E) {
    int i = blockIdx.x * blockDim.x + threadIdx.x;
    if (i < E) {
        int p = atomicAdd(&g_cur[tgt[i]], 1);
        g_edge[p] = make_int2(src[i], __float_as_int(ea[i]));
    }
}

// ---------------- fp16 split helpers ----------------
__device__ __forceinline__ void split_fp16(float v, __half& hi, __half& lo) {
    hi = __float2half_rn(v);
    lo = __float2half_rn(v - __half2float(hi));
}

// ---------------- aggregation: one warp per node, 8-edge batched ----------------
// writes plain fp16 into g_tmp row (128 halfs)
__global__ void k_agg(const float* __restrict__ h,
                      const float* __restrict__ lw, const float* __restrict__ lb,
                      const float* __restrict__ eps, int l,
                      __half* __restrict__ out, int n) {
    int warp = (blockIdx.x * blockDim.x + threadIdx.x) >> 5;
    int lane = threadIdx.x & 31;
    if (warp >= n) return;
    int s0 = g_off[warp], s1 = g_off[warp + 1];
    float4 lw4 = *(const float4*)(lw + lane * 4);
    float4 lb4 = *(const float4*)(lb + lane * 4);
    float4 acc = make_float4(0.f, 0.f, 0.f, 0.f);

    int e = s0;
    for (; e + 8 <= s1; e += 8) {
        int2 p[8];
        #pragma unroll
        for (int j = 0; j < 8; ++j) p[j] = g_edge[e + j];
        float4 hv[8];
        #pragma unroll
        for (int j = 0; j < 8; ++j)
            hv[j] = *(const float4*)(h + (size_t)p[j].x * D + lane * 4);
        #pragma unroll
        for (int j = 0; j < 8; ++j) {
            float a = __int_as_float(p[j].y);
            acc.x += fmaxf(fmaf(a, lw4.x, lb4.x) + hv[j].x, 0.f);
            acc.y += fmaxf(fmaf(a, lw4.y, lb4.y) + hv[j].y, 0.f);
            acc.z += fmaxf(fmaf(a, lw4.z, lb4.z) + hv[j].z, 0.f);
            acc.w += fmaxf(fmaf(a, lw4.w, lb4.w) + hv[j].w, 0.f);
        }
    }
    for (; e + 4 <= s1; e += 4) {
        int2 p[4];
        #pragma unroll
        for (int j = 0; j < 4; ++j) p[j] = g_edge[e + j];
        float4 hv[4];
        #pragma unroll
        for (int j = 0; j < 4; ++j)
            hv[j] = *(const float4*)(h + (size_t)p[j].x * D + lane * 4);
        #pragma unroll
        for (int j = 0; j < 4; ++j) {
            float a = __int_as_float(p[j].y);
            acc.x += fmaxf(fmaf(a, lw4.x, lb4.x) + hv[j].x, 0.f);
            acc.y += fmaxf(fmaf(a, lw4.y, lb4.y) + hv[j].y, 0.f);
            acc.z += fmaxf(fmaf(a, lw4.z, lb4.z) + hv[j].z, 0.f);
            acc.w += fmaxf(fmaf(a, lw4.w, lb4.w) + hv[j].w, 0.f);
        }
    }
    for (; e < s1; ++e) {
        int2  p = g_edge[e];
        float a = __int_as_float(p.y);
        float4 hv = *(const float4*)(h + (size_t)p.x * D + lane * 4);
        acc.x += fmaxf(fmaf(a, lw4.x, lb4.x) + hv.x, 0.f);
        acc.y += fmaxf(fmaf(a, lw4.y, lb4.y) + hv.y, 0.f);
        acc.z += fmaxf(fmaf(a, lw4.z, lb4.z) + hv.z, 0.f);
        acc.w += fmaxf(fmaf(a, lw4.w, lb4.w) + hv.w, 0.f);
    }

    float inv = 1.f / (float)(s1 - s0);
    float g   = 1.f + eps[l];
    float4 hn = *(const float4*)(h + (size_t)warp * D + lane * 4);
    __half2 pA = __floats2half2_rn(acc.x * inv + g * hn.x, acc.y * inv + g * hn.y);
    __half2 pB = __floats2half2_rn(acc.z * inv + g * hn.z, acc.w * inv + g * hn.w);
    *(uint2*)(out + (size_t)warp * 128 + lane * 4) =
        make_uint2(*(uint32_t*)&pA, *(uint32_t*)&pB);
}

// ---------------- weight prep (also zeroes g_cnt): transpose + fp16 ------
__global__ void k_wprep(const float* __restrict__ w1, const float* __restrict__ w2,
                        const float* __restrict__ fw, int n) {
    int idx = blockIdx.x * blockDim.x + threadIdx.x;     // 40 * 128 * 32 = 163840
    if (idx < n) g_cnt[idx] = 0;
    if (idx >= 40 * 128 * 32) return;
    int ch  = idx >> 12;
    int rem = idx & 4095;
    int nn  = rem >> 5;
    int kk  = rem & 31;
    const float* W;
    int kg;
    if (ch < 24) {
        int g  = ch >> 2;
        int cw = ch & 3;
        int layer = g >> 1;
        W  = (g & 1) ? (w2 + (size_t)layer * D * D) : (w1 + (size_t)layer * D * D);
        kg = cw * 32 + kk;
    } else {
        int cw = ch - 24;
        W  = fw;
        kg = cw * 32 + kk;
    }
    g_wb[ch][nn * 40 + kk] = __float2half_rn(W[(size_t)kg * 128 + nn]);
}

// ---------------- HMMA / LDSM / cp.async helpers ----------------
__device__ __forceinline__ void mma_fp16(float* c, const uint32_t* a, uint32_t b0, uint32_t b1) {
    asm volatile(
        "mma.sync.aligned.m16n8k16.row.col.f32.f16.f16.f32 "
        "{%0,%1,%2,%3}, {%4,%5,%6,%7}, {%8,%9}, {%0,%1,%2,%3};"
        : "+f"(c[0]), "+f"(c[1]), "+f"(c[2]), "+f"(c[3])
        : "r"(a[0]), "r"(a[1]), "r"(a[2]), "r"(a[3]), "r"(b0), "r"(b1));
}

__device__ __forceinline__ void ldsm_x4(uint32_t* r, uint32_t addr) {
    asm volatile("ldmatrix.sync.aligned.m8n8.x4.shared.b16 {%0,%1,%2,%3}, [%4];"
                 : "=r"(r[0]), "=r"(r[1]), "=r"(r[2]), "=r"(r[3]) : "r"(addr));
}

__device__ __forceinline__ void cpasync16(uint32_t saddr, const void* gaddr) {
    asm volatile("cp.async.cg.shared.global [%0], [%1], 16;" :: "r"(saddr), "l"(gaddr));
}
__device__ __forceinline__ void cpasync_commit() { asm volatile("cp.async.commit_group;" ::: "memory"); }
__device__ __forceinline__ void cpasync_wait0()  { asm volatile("cp.async.wait_group 0;" ::: "memory"); }

// stage one 10240B fp16 weight chunk (640 x 16B) via cp.async
__device__ __forceinline__ void stageB_async(uint32_t sbase, const __half* src, int tid) {
    #pragma unroll
    for (int i = 0; i < 3; ++i) {
        int t = tid + 256 * i;
        if (t < 640) cpasync16(sbase + t * 16, (const char*)src + t * 16);
    }
}

// pack 8 fp32 into hi/lo fp16 uint4s (final GEMM A staging)
__device__ __forceinline__ void pack8h(const float* v, uint4& hiq, uint4& loq) {
    uint32_t hw[4], lw_[4];
    #pragma unroll
    for (int q = 0; q < 4; ++q) {
        __half h0, l0, h1, l1;
        split_fp16(v[q * 2],     h0, l0);
        split_fp16(v[q * 2 + 1], h1, l1);
        __half2 hp = __halves2half2(h0, h1), lp = __halves2half2(l0, l1);
        hw[q]  = *(uint32_t*)&hp;
        lw_[q] = *(uint32_t*)&lp;
    }
    hiq = *(uint4*)hw;
    loq = *(uint4*)lw_;
}

#define SB_BUF_BYTES 10240     // 128 x 40 fp16
#define SA_BUF_BYTES 5120      // 64 x 40 fp16 (plain A, no lo)
#define SMID_BYTES 33792       // 64 x 264 fp16
#define FA_BUF_BYTES 18432     // 128 x 72 fp16

// ---------------- fused layer MLP: h = relu(A@w1+b1)@w2+b2 ----------------
// A is plain fp16 from k_agg (1 A-pass in phase 1); mid keeps hi/lo split (2 passes).
__global__ void __launch_bounds__(256) k_layer_mlp(
    const __half* __restrict__ A, int wb1, int wb2,
    const float* __restrict__ bias1, const float* __restrict__ bias2,
    float* __restrict__ Cout, int M)
{
    extern __shared__ __align__(16) char dyn[];
    __half* sU = (__half*)dyn;                       // sMid / phase-1 sA double buf
    __half* sB = (__half*)(dyn + SMID_BYTES);        // 2 x weight chunk

    const int tid  = threadIdx.x;
    const int w    = tid >> 5;
    const int lane = tid & 31;
    const int wr   = w & 1;
    const int wc   = w >> 1;
    const int gid  = lane >> 2;
    const int tg   = lane & 3;
    const int lg   = lane >> 3;
    const int lr   = lane & 7;
    const int brow = blockIdx.x * 64;

    const uint32_t sUb = (uint32_t)__cvta_generic_to_shared(sU);
    const uint32_t sBb = (uint32_t)__cvta_generic_to_shared(sB);

    const int a_row_off = (lg & 1) * 8 + lr;
    const int a_k_off   = (lg >> 1) * 8;
    const int b_n_off   = (lg >> 1) * 8 + lr;
    const int b_k_off   = (lg & 1) * 8;

    float c[2][4][4];
    #pragma unroll
    for (int mt = 0; mt < 2; ++mt)
        #pragma unroll
        for (int nt = 0; nt < 4; ++nt)
            #pragma unroll
            for (int j = 0; j < 4; ++j) c[mt][nt][j] = 0.f;

    const int arow = tid >> 2;       // 0..63
    const int aq   = (tid & 3) * 8;  // 8 fp16 per load
    const int grow = brow + arow;

    uint4 vhi;
    auto loadAchunk = [&](int ch) {
        if (grow < M) vhi = *(const uint4*)(A + (size_t)grow * 128 + ch * 32 + aq);
        else          vhi = make_uint4(0, 0, 0, 0);
    };

    // ---------- prologue: stage chunk 0 ----------
    stageB_async(sBb, g_wb[wb1], tid);
    cpasync_commit();
    loadAchunk(0);
    *(uint4*)&sU[arow * 40 + aq] = vhi;
    cpasync_wait0();
    __syncthreads();

    // ================= phase 1: mid = A @ w1 (4 chunks, 1 A-pass) ============
    int buf = 0;
    for (int ch = 0; ch < 4; ++ch) {
        const bool more = (ch < 3);
        stageB_async(sBb + (buf ^ 1) * SB_BUF_BYTES,
                     more ? g_wb[wb1 + ch + 1] : g_wb[wb2], tid);
        cpasync_commit();
        if (more) loadAchunk(ch + 1);
        const uint32_t aB = sUb + buf * SA_BUF_BYTES;
        const uint32_t bB = sBb + buf * SB_BUF_BYTES;
        #pragma unroll
        for (int ks = 0; ks < 2; ++ks) {
            uint32_t b[2][4];
            #pragma unroll
            for (int np = 0; np < 2; ++np)
                ldsm_x4(b[np], bB + ((wc * 32 + np * 16 + b_n_off) * 40 + ks * 16 + b_k_off) * 2);
            uint32_t a[2][4];
            #pragma unroll
            for (int mt = 0; mt < 2; ++mt)
                ldsm_x4(a[mt], aB + ((wr * 32 + mt * 16 + a_row_off) * 40 + ks * 16 + a_k_off) * 2);
            #pragma unroll
            for (int np = 0; np < 2; ++np) {
                mma_fp16(c[0][np * 2],     a[0], b[np][0], b[np][1]);
                mma_fp16(c[1][np * 2],     a[1], b[np][0], b[np][1]);
                mma_fp16(c[0][np * 2 + 1], a[0], b[np][2], b[np][3]);
                mma_fp16(c[1][np * 2 + 1], a[1], b[np][2], b[np][3]);
            }
        }
        if (more) {
            __half* sA1 = sU + (buf ^ 1) * (SA_BUF_BYTES / 2);
            *(uint4*)&sA1[arow * 40 + aq] = vhi;
        }
        cpasync_wait0();
        __syncthreads();
        buf ^= 1;
    }
    // buf now points at the staged w2 chunk 0.

    // ============ epilogue 1: bias + relu + fp16 split -> sMid ============
    float c2[2][4][4];
    #pragma unroll
    for (int mt = 0; mt < 2; ++mt) {
        #pragma unroll
        for (int nt = 0; nt < 4; ++nt) {
            int col = wc * 32 + nt * 8 + tg * 2;
            float bx = bias1[col], by = bias1[col + 1];
            #pragma unroll
            for (int half = 0; half < 2; ++half) {
                int r = wr * 32 + mt * 16 + gid + half * 8;
                float v0 = fmaxf(c[mt][nt][half * 2]     + bx, 0.f);
                float v1 = fmaxf(c[mt][nt][half * 2 + 1] + by, 0.f);
                __half h0, l0, h1, l1;
                split_fp16(v0, h0, l0);
                split_fp16(v1, h1, l1);
                __half2 hp = __halves2half2(h0, h1), lp = __halves2half2(l0, l1);
                *(uint32_t*)&sU[r * 264 + col]       = *(uint32_t*)&hp;
                *(uint32_t*)&sU[r * 264 + 128 + col] = *(uint32_t*)&lp;
            }
            #pragma unroll
            for (int j = 0; j < 4; ++j) c2[mt][nt][j] = 0.f;
        }
    }
    __syncthreads();

    // ================= phase 2: h = mid @ w2 (4 chunks; buf holds w2[0]) ============
    for (int ch = 0; ch < 4; ++ch) {
        if (ch < 3) {
            stageB_async(sBb + (buf ^ 1) * SB_BUF_BYTES, g_wb[wb2 + ch + 1], tid);
            cpasync_commit();
        }
        const uint32_t bB = sBb + buf * SB_BUF_BYTES;
        #pragma unroll
        for (int ks = 0; ks < 2; ++ks) {
            uint32_t b[2][4];
            #pragma unroll
            for (int np = 0; np < 2; ++np)
                ldsm_x4(b[np], bB + ((wc * 32 + np * 16 + b_n_off) * 40 + ks * 16 + b_k_off) * 2);
            #pragma unroll
            for (int p = 0; p < 2; ++p) {
                const int ak = ch * 32 + ks * 16 + p * 128;
                uint32_t a[2][4];
                #pragma unroll
                for (int mt = 0; mt < 2; ++mt)
                    ldsm_x4(a[mt], sUb + ((wr * 32 + mt * 16 + a_row_off) * 264 + ak + a_k_off) * 2);
                #pragma unroll
                for (int np = 0; np < 2; ++np) {
                    mma_fp16(c2[0][np * 2],     a[0], b[np][0], b[np][1]);
                    mma_fp16(c2[1][np * 2],     a[1], b[np][0], b[np][1]);
                    mma_fp16(c2[0][np * 2 + 1], a[0], b[np][2], b[np][3]);
                    mma_fp16(c2[1][np * 2 + 1], a[1], b[np][2], b[np][3]);
                }
            }
        }
        if (ch < 3) {
            cpasync_wait0();
            __syncthreads();
        }
        buf ^= 1;
    }

    // ============ epilogue 2: bias2 -> global ============
    #pragma unroll
    for (int mt = 0; mt < 2; ++mt) {
        #pragma unroll
        for (int nt = 0; nt < 4; ++nt) {
            int col = wc * 32 + nt * 8 + tg * 2;
            float bx = bias2[col], by = bias2[col + 1];
            int r0 = brow + wr * 32 + mt * 16 + gid;
            float v0 = c2[mt][nt][0] + bx, v1 = c2[mt][nt][1] + by;
            float v2 = c2[mt][nt][2] + bx, v3 = c2[mt][nt][3] + by;
            if (r0 < M)     *(float2*)(Cout + (size_t)r0 * D + col)       = make_float2(v0, v1);
            if (r0 + 8 < M) *(float2*)(Cout + (size_t)(r0 + 8) * D + col) = make_float2(v2, v3);
        }
    }
}

// ---------------- final GEMM: C = concat(A0..A3) @ W + bias (pipelined) ----
__global__ void __launch_bounds__(256) k_gemm_final(
    const float* __restrict__ A0, const float* __restrict__ A1,
    const float* __restrict__ A2, const float* __restrict__ A3,
    int wbase, const float* __restrict__ bias, float* __restrict__ C, int M)
{
    extern __shared__ __align__(16) char dyn[];
    __half* sA = (__half*)dyn;                        // 2 x 128*72
    __half* sB = (__half*)(dyn + 2 * FA_BUF_BYTES);   // 2 x 128*40

    const int tid  = threadIdx.x;
    const int w    = tid >> 5;
    const int lane = tid & 31;
    const int wr   = w & 3;
    const int wc   = w >> 2;
    const int gid  = lane >> 2;
    const int tg   = lane & 3;
    const int lg   = lane >> 3;
    const int lr   = lane & 7;
    const int brow = blockIdx.x * 128;

    const uint32_t sAb = (uint32_t)__cvta_generic_to_shared(sA);
    const uint32_t sBb = (uint32_t)__cvta_generic_to_shared(sB);

    const int a_row_off = (lg & 1) * 8 + lr;
    const int a_k_off   = (lg >> 1) * 8;
    const int b_n_off   = (lg >> 1) * 8 + lr;
    const int b_k_off   = (lg & 1) * 8;

    const float* srcs[4] = {A0, A1, A2, A3};

    float c[2][8][4];
    #pragma unroll
    for (int mt = 0; mt < 2; ++mt)
        #pragma unroll
        for (int nt = 0; nt < 8; ++nt)
            #pragma unroll
            for (int j = 0; j < 4; ++j) c[mt][nt][j] = 0.f;

    const int arow = tid >> 1;          // 0..127
    const int aq   = (tid & 1) * 16;    // 16 fp32 each
    const int grow = brow + arow;

    float v[16];
    auto loadA = [&](int ch) {
        if (grow < M) {
            const float* ap = srcs[ch >> 2] + (size_t)grow * D + (ch & 3) * 32 + aq;
            #pragma unroll
            for (int i = 0; i < 4; ++i) {
                float4 f = *(const float4*)(ap + i * 4);
                v[i * 4 + 0] = f.x; v[i * 4 + 1] = f.y; v[i * 4 + 2] = f.z; v[i * 4 + 3] = f.w;
            }
        } else {
            #pragma unroll
            for (int i = 0; i < 16; ++i) v[i] = 0.f;
        }
    };
    auto storeA = [&](int b) {
        __half* dst = sA + b * (FA_BUF_BYTES / 2);
        uint4 hiq, loq;
        pack8h(v, hiq, loq);
        *(uint4*)&dst[arow * 72 + aq]      = hiq;
        *(uint4*)&dst[arow * 72 + 32 + aq] = loq;
        pack8h(v + 8, hiq, loq);
        *(uint4*)&dst[arow * 72 + aq + 8]      = hiq;
        *(uint4*)&dst[arow * 72 + 32 + aq + 8] = loq;
    };

    // ---------- prologue ----------
    stageB_async(sBb, g_wb[wbase], tid);
    cpasync_commit();
    loadA(0);
    storeA(0);
    cpasync_wait0();
    __syncthreads();

    int buf = 0;
    for (int ch = 0; ch < 16; ++ch) {
        const bool more = (ch < 15);
        if (more) {
            stageB_async(sBb + (buf ^ 1) * SB_BUF_BYTES, g_wb[wbase + ch + 1], tid);
            cpasync_commit();
            loadA(ch + 1);
        }
        const uint32_t aB = sAb + buf * FA_BUF_BYTES;
        const uint32_t bB = sBb + buf * SB_BUF_BYTES;
        #pragma unroll
        for (int ks = 0; ks < 2; ++ks) {
            uint32_t b[4][4];
            #pragma unroll
            for (int np = 0; np < 4; ++np)
                ldsm_x4(b[np], bB + ((wc * 64 + np * 16 + b_n_off) * 40 + ks * 16 + b_k_off) * 2);
            #pragma unroll
            for (int p = 0; p < 2; ++p) {
                const int ak = p * 32 + ks * 16;
                uint32_t a[2][4];
                #pragma unroll
                for (int mt = 0; mt < 2; ++mt)
                    ldsm_x4(a[mt], aB + ((wr * 32 + mt * 16 + a_row_off) * 72 + ak + a_k_off) * 2);
                #pragma unroll
                for (int np = 0; np < 4; ++np) {
                    mma_fp16(c[0][np * 2],     a[0], b[np][0], b[np][1]);
                    mma_fp16(c[1][np * 2],     a[1], b[np][0], b[np][1]);
                    mma_fp16(c[0][np * 2 + 1], a[0], b[np][2], b[np][3]);
                    mma_fp16(c[1][np * 2 + 1], a[1], b[np][2], b[np][3]);
                }
            }
        }
        if (more) storeA(buf ^ 1);
        cpasync_wait0();
        __syncthreads();
        buf ^= 1;
    }

    #pragma unroll
    for (int mt = 0; mt < 2; ++mt) {
        #pragma unroll
        for (int nt = 0; nt < 8; ++nt) {
            int col  = wc * 64 + nt * 8 + tg * 2;
            float bx = bias[col], by = bias[col + 1];
            int r0 = brow + wr * 32 + mt * 16 + gid;
            float v0 = c[mt][nt][0] + bx, v1 = c[mt][nt][1] + by;
            float v2 = c[mt][nt][2] + bx, v3 = c[mt][nt][3] + by;
            if (r0 < M)     *(float2*)(C + (size_t)r0 * D + col)       = make_float2(v0, v1);
            if (r0 + 8 < M) *(float2*)(C + (size_t)(r0 + 8) * D + col) = make_float2(v2, v3);
        }
    }
}

// ---------------- launcher ----------------
extern "C" void kernel_launch(void* const* d_in, const int* in_sizes, int n_in,
                              void* d_out, int out_size) {
    const float* x   = (const float*)d_in[0];
    const int*   ei  = (const int*)  d_in[1];
    const float* ea  = (const float*)d_in[2];
    const float* lw  = (const float*)d_in[3];
    const float* lb  = (const float*)d_in[4];
    const float* eps = (const float*)d_in[5];
    const float* w1  = (const float*)d_in[6];
    const float* b1  = (const float*)d_in[7];
    const float* w2  = (const float*)d_in[8];
    const float* b2  = (const float*)d_in[9];
    const float* fw  = (const float*)d_in[10];
    const float* fb  = (const float*)d_in[11];
    float* out = (float*)d_out;

    const int N = in_sizes[0] / D;
    const int E = in_sizes[2];

    const int MLP_SMEM   = SMID_BYTES + 2 * SB_BUF_BYTES;       // 54272
    const int FINAL_SMEM = 2 * FA_BUF_BYTES + 2 * SB_BUF_BYTES; // 57344
    cudaFuncSetAttribute(k_layer_mlp,  cudaFuncAttributeMaxDynamicSharedMemorySize, MLP_SMEM);
    cudaFuncSetAttribute(k_gemm_final, cudaFuncAttributeMaxDynamicSharedMemorySize, FINAL_SMEM);

    float* hbuf;
    __half* tmp;
    cudaGetSymbolAddress((void**)&hbuf, g_h);
    cudaGetSymbolAddress((void**)&tmp,  g_tmp);

    // weight prep (also zeroes g_cnt) + CSR build (fused scan)
    k_wprep<<<(40 * 128 * 32 + 255) / 256, 256>>>(w1, w2, fw, N);
    k_hist<<<(E + 255) / 256, 256>>>(ei + E, E);
    const int nb = (N + 1023) / 1024;
    k_scan<<<nb, 1024>>>(N, nb);
    k_scatter<<<(E + 255) / 256, 256>>>(ei, ei + E, ea, E);

    const float* h = x;
    for (int l = 0; l < 3; ++l) {
        float* hl = hbuf + (size_t)l * NMAX * D;
        k_agg<<<(N + 7) / 8, 256>>>(h, lw + l * D, lb + l * D, eps, l, tmp, N);
        k_layer_mlp<<<(N + 63) / 64, 256, MLP_SMEM>>>(tmp, (l * 2 + 0) * 4, (l * 2 + 1) * 4,
                                                      b1 + l * D, b2 + l * D, hl, N);
        h = hl;
    }

    // final: [x | h1 | h2 | h3] @ fw + fb
    k_gemm_final<<<(N + 127) / 128, 256, FINAL_SMEM>>>(x, hbuf, hbuf + (size_t)NMAX * D,
                                                       hbuf + (size_t)2 * NMAX * D, 24, fb, out, N);
}